// round 6
// baseline (speedup 1.0000x reference)
#include <cuda_runtime.h>

#define FULLM 0xffffffffu
#define B_N 1024
#define L_N 1024
#define T_N 21

__device__ double g_sum;
__device__ double g_cnt;

__global__ void init_k() { g_sum = 0.0; g_cnt = 0.0; }

typedef unsigned long long ull;

__device__ __forceinline__ ull pk2(float lo, float hi) {
    ull r; asm("mov.b64 %0, {%1, %2};" : "=l"(r) : "f"(lo), "f"(hi)); return r;
}
__device__ __forceinline__ void fma2(ull& a, ull x, ull y) {
    asm("fma.rn.f32x2 %0, %1, %2, %0;" : "+l"(a) : "l"(x), "l"(y));
}
__device__ __forceinline__ ull add2(ull x, ull y) {
    ull r; asm("add.rn.f32x2 %0, %1, %2;" : "=l"(r) : "l"(x), "l"(y)); return r;
}
__device__ __forceinline__ void unpk(ull v, float& lo, float& hi) {
    asm("mov.b64 {%0, %1}, %2;" : "=f"(lo), "=f"(hi) : "l"(v));
}

// 128-thread blocks: 4 warps, ONE SEQUENCE PER WARP (warps spread across all
// 4 SMSPs -- 32-thread blocks pile every warp onto SMSP 0 via wid%4).
// Lane j of each warp owns alpha[j] (j<21); broadcast via per-warp
// double-buffered smem row: 1 STS + block BAR(7cyc) + 6 LDS.128.
__global__ __launch_bounds__(128) void crf_k(
    const float* __restrict__ em, const int* __restrict__ tags,
    const int* __restrict__ mask,
    const float* __restrict__ startv, const float* __restrict__ endv,
    const float* __restrict__ transv)
{
    __shared__ float4 abuf[4][2][6];   // [warp][parity][24 floats]
    int tid = threadIdx.x;
    int lane = tid & 31;
    int w = tid >> 5;
    int seq = blockIdx.x * 4 + w;
    bool act = lane < T_N;
    int j = act ? lane : (T_N - 1);

    // E columns packed as 12 f32x2 pairs (rows 21..23 are zero).
    ull ep[12];
    {
        float c[24];
        #pragma unroll
        for (int s = 0; s < 24; s++)
            c[s] = (s < T_N && act) ? __expf(__ldg(transv + s * T_N + lane)) : 0.f;
        #pragma unroll
        for (int m = 0; m < 12; m++) ep[m] = pk2(c[2*m], c[2*m+1]);
    }

    const float* pe = em + (size_t)seq * (L_N * T_N);
    const int* tg = tags + (size_t)seq * L_N;
    const int* mk = mask + (size_t)seq * L_N;

    // zero the pad entries (21..23) of both buffers, written once
    if (lane >= T_N && lane < 24) {
        ((float*)abuf[w][0])[lane] = 0.f;
        ((float*)abuf[w][1])[lane] = 0.f;
    }

    // ---- t = 0 ----
    float em0 = __ldg(pe + j);
    float newv = act ? __expf(__ldg(startv + j) + em0) : 0.f;
    if (act) ((float*)abuf[w][0])[lane] = newv;
    __syncthreads();

    float logZ = 0.f;
    int tg0 = __ldg(tg);
    float score = __ldg(startv + tg0) + __ldg(pe + tg0);
    int cnt = __ldg(mk) ? 1 : 0;
    int prev = tg0;

    // emission software pipeline, depth 8 (rows 1..8)
    float ebuf[8];
    #pragma unroll
    for (int k = 0; k < 8; k++) ebuf[k] = __ldg(pe + (size_t)(1 + k) * T_N + j);

    float inv = 1.f, lg = 0.f;

    auto STEP = [&](int t, int ct, int m, bool do_renorm, bool prep_renorm) {
        float cur = ebuf[(t - 1) & 7];
        if (t + 8 < L_N) ebuf[(t - 1) & 7] = __ldg(pe + (size_t)(t + 8) * T_N + j);
        float p = __expf(cur);

        const float4* rb = abuf[w][(t - 1) & 1];
        float4 v0 = rb[0], v1 = rb[1], v2 = rb[2];
        float4 v3 = rb[3], v4 = rb[4], v5 = rb[5];

        if (prep_renorm) { inv = __fdividef(1.f, v0.x); lg = __logf(v0.x); }

        ull a0 = 0ull, a1 = 0ull, a2 = 0ull;
        fma2(a0, pk2(v0.x, v0.y), ep[0]);  fma2(a1, pk2(v0.z, v0.w), ep[1]);
        fma2(a2, pk2(v1.x, v1.y), ep[2]);  fma2(a0, pk2(v1.z, v1.w), ep[3]);
        fma2(a1, pk2(v2.x, v2.y), ep[4]);  fma2(a2, pk2(v2.z, v2.w), ep[5]);
        fma2(a0, pk2(v3.x, v3.y), ep[6]);  fma2(a1, pk2(v3.z, v3.w), ep[7]);
        fma2(a2, pk2(v4.x, v4.y), ep[8]);  fma2(a0, pk2(v4.z, v4.w), ep[9]);
        fma2(a1, pk2(v5.x, v5.y), ep[10]); fma2(a2, pk2(v5.z, v5.w), ep[11]);
        ull at = add2(add2(a0, a1), a2);
        float lo, hi; unpk(at, lo, hi);
        float nxt = (lo + hi) * p;

        // numerator (uniform across warp; L1-hit broadcast loads)
        float ltr = __ldg(transv + prev * T_N + ct);
        float emt = __ldg(pe + (size_t)t * T_N + ct);
        if (m) { score += ltr + emt; cnt++; }

        float out = m ? nxt : newv;
        if (do_renorm) { out *= inv; logZ += lg; }
        newv = out;
        if (act) ((float*)abuf[w][t & 1])[lane] = out;
        __syncthreads();
        prev = ct;
    };

    {   // chunk 0: steps 1..3
        int4 tc = __ldg((const int4*)tg);
        int4 mc = __ldg((const int4*)mk);
        STEP(1, tc.y, mc.y, false, false);
        STEP(2, tc.z, mc.z, false, false);
        STEP(3, tc.w, mc.w, false, true);
    }
    for (int c4 = 1; c4 < L_N / 4; c4++) {
        int4 tc = __ldg((const int4*)(tg + 4 * c4));
        int4 mc = __ldg((const int4*)(mk + 4 * c4));
        int tb = 4 * c4;
        STEP(tb + 0, tc.x, mc.x, true,  false);
        STEP(tb + 1, tc.y, mc.y, false, false);
        STEP(tb + 2, tc.z, mc.z, false, false);
        STEP(tb + 3, tc.w, mc.w, false, true);
    }

    // denominator: v = sum_j alpha_j * exp(end_j)   (alpha scaled; logZ holds the rest)
    float v = act ? newv * __expf(__ldg(endv + j)) : 0.f;
    #pragma unroll
    for (int off = 16; off > 0; off >>= 1) v += __shfl_xor_sync(FULLM, v, off);
    float denom = logZ + __logf(v);

    int li = cnt > 0 ? cnt - 1 : 0;
    score += __ldg(endv + __ldg(tg + li));

    if (lane == 0) {
        atomicAdd(&g_sum, (double)(score - denom));
        atomicAdd(&g_cnt, (double)cnt);
    }
}

__global__ void fin_k(float* out) { out[0] = (float)(g_sum / g_cnt); }

extern "C" void kernel_launch(void* const* d_in, const int* in_sizes, int n_in,
                              void* d_out, int out_size) {
    const float* em     = (const float*)d_in[0];
    const int* tags     = (const int*)d_in[1];
    const int* mask     = (const int*)d_in[2];
    const float* startv = (const float*)d_in[3];
    const float* endv   = (const float*)d_in[4];
    const float* trans  = (const float*)d_in[5];

    init_k<<<1, 1>>>();
    crf_k<<<B_N / 4, 128>>>(em, tags, mask, startv, endv, trans);
    fin_k<<<1, 1>>>((float*)d_out);
}

// round 8
// speedup vs baseline: 1.3324x; 1.3324x over previous
#include <cuda_runtime.h>

#define FULLM 0xffffffffu
#define B_N 1024
#define L_N 1024
#define T_N 21

__device__ double g_sum;
__device__ double g_cnt;

__global__ void init_k() { g_sum = 0.0; g_cnt = 0.0; }

typedef unsigned long long ull;

__device__ __forceinline__ ull pk2(float lo, float hi) {
    ull r; asm("mov.b64 %0, {%1, %2};" : "=l"(r) : "f"(lo), "f"(hi)); return r;
}
__device__ __forceinline__ void fma2(ull& a, ull x, ull y) {
    asm("fma.rn.f32x2 %0, %1, %2, %0;" : "+l"(a) : "l"(x), "l"(y));
}
__device__ __forceinline__ ull add2(ull x, ull y) {
    ull r; asm("add.rn.f32x2 %0, %1, %2;" : "=l"(r) : "l"(x), "l"(y)); return r;
}
__device__ __forceinline__ void unpk(ull v, float& lo, float& hi) {
    asm("mov.b64 {%0, %1}, %2;" : "=f"(lo), "=f"(hi) : "l"(v));
}

// 128-thread blocks: 4 warps, one sequence per warp (SMSP spread via wid%4).
// Per-warp PRIVATE double-buffered smem broadcast of alpha:
// 1 STS + __syncwarp + 6 LDS.128 (read as ulonglong2 -> pre-packed f32x2 pairs).
// No block-wide barrier in the mainloop: warps slide independently.
__global__ __launch_bounds__(128) void crf_k(
    const float* __restrict__ em, const int* __restrict__ tags,
    const int* __restrict__ mask,
    const float* __restrict__ startv, const float* __restrict__ endv,
    const float* __restrict__ transv)
{
    __shared__ ulonglong2 abuf[4][2][6];   // [warp][parity][6 x 16B = 24 floats]
    int tid = threadIdx.x;
    int lane = tid & 31;
    int w = tid >> 5;
    int seq = blockIdx.x * 4 + w;
    bool act = lane < T_N;
    int j = act ? lane : (T_N - 1);

    // E columns packed as 12 f32x2 pairs (rows 21..23 are zero).
    ull ep[12];
    {
        float c[24];
        #pragma unroll
        for (int s = 0; s < 24; s++)
            c[s] = (s < T_N && act) ? __expf(__ldg(transv + s * T_N + lane)) : 0.f;
        #pragma unroll
        for (int m = 0; m < 12; m++) ep[m] = pk2(c[2*m], c[2*m+1]);
    }

    const float* pe = em + (size_t)seq * (L_N * T_N);
    const int* tg = tags + (size_t)seq * L_N;
    const int* mk = mask + (size_t)seq * L_N;

    // zero the pad entries (21..23) of both buffers, written once
    if (lane >= T_N && lane < 24) {
        ((float*)abuf[w][0])[lane] = 0.f;
        ((float*)abuf[w][1])[lane] = 0.f;
    }

    // ---- t = 0 ----
    float em0 = __ldg(pe + j);
    float newv = act ? __expf(__ldg(startv + j) + em0) : 0.f;
    if (act) ((float*)abuf[w][0])[lane] = newv;
    __syncwarp();

    float logZ = 0.f;
    int tg0 = __ldg(tg);
    float score = __ldg(startv + tg0) + __ldg(pe + tg0);
    int cnt = __ldg(mk) ? 1 : 0;
    int prev = tg0;

    // emission software pipeline, depth 8 (rows 1..8)
    float ebuf[8];
    #pragma unroll
    for (int k = 0; k < 8; k++) ebuf[k] = __ldg(pe + (size_t)(1 + k) * T_N + j);

    float inv = 1.f, lg = 0.f;

    auto STEP = [&](int t, int ct, int m, bool do_renorm, bool prep_renorm) {
        float cur = ebuf[(t - 1) & 7];
        if (t + 8 < L_N) ebuf[(t - 1) & 7] = __ldg(pe + (size_t)(t + 8) * T_N + j);
        float p = __expf(cur);

        const ulonglong2* rb = abuf[w][(t - 1) & 1];
        ulonglong2 q0 = rb[0], q1 = rb[1], q2 = rb[2];
        ulonglong2 q3 = rb[3], q4 = rb[4], q5 = rb[5];

        if (prep_renorm) {
            float z0, z1; unpk(q0.x, z0, z1);
            inv = __fdividef(1.f, z0); lg = __logf(z0);
        }

        ull a0 = 0ull, a1 = 0ull, a2 = 0ull;
        fma2(a0, q0.x, ep[0]);  fma2(a1, q0.y, ep[1]);
        fma2(a2, q1.x, ep[2]);  fma2(a0, q1.y, ep[3]);
        fma2(a1, q2.x, ep[4]);  fma2(a2, q2.y, ep[5]);
        fma2(a0, q3.x, ep[6]);  fma2(a1, q3.y, ep[7]);
        fma2(a2, q4.x, ep[8]);  fma2(a0, q4.y, ep[9]);
        fma2(a1, q5.x, ep[10]); fma2(a2, q5.y, ep[11]);
        ull at = add2(add2(a0, a1), a2);
        float lo, hi; unpk(at, lo, hi);
        float nxt = (lo + hi) * p;

        // numerator (uniform across warp; L1-hit broadcast loads)
        float ltr = __ldg(transv + prev * T_N + ct);
        float emt = __ldg(pe + (size_t)t * T_N + ct);
        if (m) { score += ltr + emt; cnt++; }

        float out = m ? nxt : newv;
        if (do_renorm) { out *= inv; logZ += lg; }
        newv = out;
        if (act) ((float*)abuf[w][t & 1])[lane] = out;
        __syncwarp();
        prev = ct;
    };

    {   // chunk 0: steps 1..3
        int4 tc = __ldg((const int4*)tg);
        int4 mc = __ldg((const int4*)mk);
        STEP(1, tc.y, mc.y, false, false);
        STEP(2, tc.z, mc.z, false, false);
        STEP(3, tc.w, mc.w, false, true);
    }
    for (int c4 = 1; c4 < L_N / 4; c4++) {
        int4 tc = __ldg((const int4*)(tg + 4 * c4));
        int4 mc = __ldg((const int4*)(mk + 4 * c4));
        int tb = 4 * c4;
        STEP(tb + 0, tc.x, mc.x, true,  false);
        STEP(tb + 1, tc.y, mc.y, false, false);
        STEP(tb + 2, tc.z, mc.z, false, false);
        STEP(tb + 3, tc.w, mc.w, false, true);
    }

    // denominator: v = sum_j alpha_j * exp(end_j)   (alpha scaled; logZ holds the rest)
    float v = act ? newv * __expf(__ldg(endv + j)) : 0.f;
    #pragma unroll
    for (int off = 16; off > 0; off >>= 1) v += __shfl_xor_sync(FULLM, v, off);
    float denom = logZ + __logf(v);

    int li = cnt > 0 ? cnt - 1 : 0;
    score += __ldg(endv + __ldg(tg + li));

    if (lane == 0) {
        atomicAdd(&g_sum, (double)(score - denom));
        atomicAdd(&g_cnt, (double)cnt);
    }
}

__global__ void fin_k(float* out) { out[0] = (float)(g_sum / g_cnt); }

extern "C" void kernel_launch(void* const* d_in, const int* in_sizes, int n_in,
                              void* d_out, int out_size) {
    const float* em     = (const float*)d_in[0];
    const int* tags     = (const int*)d_in[1];
    const int* mask     = (const int*)d_in[2];
    const float* startv = (const float*)d_in[3];
    const float* endv   = (const float*)d_in[4];
    const float* trans  = (const float*)d_in[5];

    init_k<<<1, 1>>>();
    crf_k<<<B_N / 4, 128>>>(em, tags, mask, startv, endv, trans);
    fin_k<<<1, 1>>>((float*)d_out);
}

// round 10
// speedup vs baseline: 1.5614x; 1.1719x over previous
#include <cuda_runtime.h>

#define FULLM 0xffffffffu
#define B_N 1024
#define L_N 1024
#define T_N 21

typedef unsigned long long ull;

__device__ double g_ps[256];
__device__ double g_pc[256];
__device__ unsigned int g_ctr;   // static zero-init; self-resetting

__device__ __forceinline__ ull pk2(float lo, float hi) {
    ull r; asm("mov.b64 %0, {%1, %2};" : "=l"(r) : "f"(lo), "f"(hi)); return r;
}
__device__ __forceinline__ void fma2(ull& a, ull x, ull y) {
    asm("fma.rn.f32x2 %0, %1, %2, %0;" : "+l"(a) : "l"(x), "l"(y));
}
__device__ __forceinline__ ull add2(ull x, ull y) {
    ull r; asm("add.rn.f32x2 %0, %1, %2;" : "=l"(r) : "l"(x), "l"(y)); return r;
}
__device__ __forceinline__ void unpk(ull v, float& lo, float& hi) {
    asm("mov.b64 {%0, %1}, %2;" : "=f"(lo), "=f"(hi) : "l"(v));
}

// 128-thr blocks, 4 warps, one sequence per warp. Each warp runs the forward
// recursion (t=1..511) and backward recursion (t=1023..512) INTERLEAVED:
// halved serial chain, doubled ILP, one __syncwarp per (fwd,bwd) pair.
// Branch-free mainloop: all 32 lanes store (inactive lanes carry exact 0),
// emission refills unconditional (index ranges always valid).
__global__ __launch_bounds__(128) void crf_k(
    const float* __restrict__ em, const int* __restrict__ tags,
    const int* __restrict__ mask,
    const float* __restrict__ startv, const float* __restrict__ endv,
    const float* __restrict__ transv,
    float* __restrict__ out)
{
    __shared__ ulonglong2 abuf[4][2][2][8];  // [warp][chain F=0/B=1][parity][32 floats]
    __shared__ double s_s[4], s_c[4];
    __shared__ int s_last;

    int tid = threadIdx.x;
    int lane = tid & 31;
    int w = tid >> 5;
    int seq = blockIdx.x * 4 + w;
    bool act = lane < T_N;
    int j = act ? lane : (T_N - 1);

    // ep: fwd needs column j of E=exp(trans); er: bwd needs row 'lane' of E.
    ull ep[12], er[12];
    {
        float c[24], r[24];
        #pragma unroll
        for (int s = 0; s < 24; s++) {
            c[s] = (s < T_N && act) ? __expf(__ldg(transv + s * T_N + lane)) : 0.f;
            r[s] = (s < T_N && act) ? __expf(__ldg(transv + lane * T_N + s)) : 0.f;
        }
        #pragma unroll
        for (int m = 0; m < 12; m++) { ep[m] = pk2(c[2*m], c[2*m+1]); er[m] = pk2(r[2*m], r[2*m+1]); }
    }

    const float* pe = em + (size_t)seq * (L_N * T_N);
    const int* tg = tags + (size_t)seq * L_N;
    const int* mk = mask + (size_t)seq * L_N;

    ulonglong2 (*bF)[8] = abuf[w][0];
    ulonglong2 (*bB)[8] = abuf[w][1];

    // ---- forward init (t=0) ----
    float em0 = __ldg(pe + j);
    float newvF = act ? __expf(__ldg(startv + j) + em0) : 0.f;
    ((float*)bF[0])[lane] = newvF;

    // ---- backward init (t=1023): state beta=exp(end); broadcast y=p*beta ----
    float newvB = act ? __expf(__ldg(endv + j)) : 0.f;
    {
        float e1023 = __ldg(pe + (size_t)1023 * T_N + j);
        float y = __expf(e1023) * newvB;
        ((float*)bB[1])[lane] = y;
    }

    // emission pipelines: fwd rows 1..8; bwd rows 1015..1022 (slot = row&7)
    float ebF[8], ebB[8];
    #pragma unroll
    for (int k = 0; k < 8; k++) {
        ebF[k] = __ldg(pe + (size_t)(1 + k) * T_N + j);
        int r = 1015 + k;
        ebB[r & 7] = __ldg(pe + (size_t)r * T_N + j);
    }
    __syncwarp();

    float score, logZf = 0.f, logZb = 0.f;
    float invF = 1.f, lgF = 0.f, invB = 1.f, lgB = 0.f;
    int cnt, prevF;

    auto STEPF = [&](int t, int ct, int m, bool do_rn, bool prep_rn) {
        float cur = ebF[(t - 1) & 7];
        ebF[(t - 1) & 7] = __ldg(pe + (size_t)(t + 8) * T_N + j);   // t+8 <= 519, always valid
        float p = __expf(cur);
        const ulonglong2* rb = bF[(t - 1) & 1];
        ulonglong2 q0 = rb[0], q1 = rb[1], q2 = rb[2], q3 = rb[3], q4 = rb[4], q5 = rb[5];
        if (prep_rn) { float z0, z1; unpk(q0.x, z0, z1); invF = __fdividef(1.f, z0); lgF = __logf(z0); }
        ull a0 = 0ull, a1 = 0ull, a2 = 0ull;
        fma2(a0, q0.x, ep[0]);  fma2(a1, q0.y, ep[1]);
        fma2(a2, q1.x, ep[2]);  fma2(a0, q1.y, ep[3]);
        fma2(a1, q2.x, ep[4]);  fma2(a2, q2.y, ep[5]);
        fma2(a0, q3.x, ep[6]);  fma2(a1, q3.y, ep[7]);
        fma2(a2, q4.x, ep[8]);  fma2(a0, q4.y, ep[9]);
        fma2(a1, q5.x, ep[10]); fma2(a2, q5.y, ep[11]);
        ull at = add2(add2(a0, a1), a2);
        float lo, hi; unpk(at, lo, hi);
        float nxt = (lo + hi) * p;
        float ltr = __ldg(transv + prevF * T_N + ct);
        float emt = __ldg(pe + (size_t)t * T_N + ct);
        score += m ? (ltr + emt) : 0.f;
        cnt += m;
        newvF = m ? nxt : newvF;
        if (do_rn) { newvF *= invF; logZf += lgF; }
        ((float*)bF[t & 1])[lane] = newvF;
        prevF = ct;
    };

    auto STEPB = [&](int t, int ct, int ctm1, int m, bool do_rn, bool prep_rn, bool last) {
        const ulonglong2* rb = bB[t & 1];
        ulonglong2 q0 = rb[0], q1 = rb[1], q2 = rb[2], q3 = rb[3], q4 = rb[4], q5 = rb[5];
        if (prep_rn) { float z0, z1; unpk(q0.x, z0, z1); invB = __fdividef(1.f, z0); lgB = __logf(z0); }
        ull a0 = 0ull, a1 = 0ull, a2 = 0ull;
        fma2(a0, q0.x, er[0]);  fma2(a1, q0.y, er[1]);
        fma2(a2, q1.x, er[2]);  fma2(a0, q1.y, er[3]);
        fma2(a1, q2.x, er[4]);  fma2(a2, q2.y, er[5]);
        fma2(a0, q3.x, er[6]);  fma2(a1, q3.y, er[7]);
        fma2(a2, q4.x, er[8]);  fma2(a0, q4.y, er[9]);
        fma2(a1, q5.x, er[10]); fma2(a2, q5.y, er[11]);
        ull at = add2(add2(a0, a1), a2);
        float lo, hi; unpk(at, lo, hi);
        float dotB = lo + hi;
        float ltr = __ldg(transv + ctm1 * T_N + ct);
        float emt = __ldg(pe + (size_t)t * T_N + ct);
        score += m ? (ltr + emt) : 0.f;
        cnt += m;
        newvB = m ? dotB : newvB;
        if (do_rn) { newvB *= invB; logZb += lgB; }
        if (!last) {
            float eb = ebB[(t - 1) & 7];
            ebB[(t - 1) & 7] = __ldg(pe + (size_t)(t - 9) * T_N + j);  // t-9 >= 504, valid
            float y = __expf(eb) * newvB;
            ((float*)bB[(t - 1) & 1])[lane] = y;
        }
    };

    int4 tBcur;
    {   // merged chunk 0: fwd t=1..3, bwd t=1023..1020
        int4 tc = __ldg((const int4*)tg);
        int4 mc = __ldg((const int4*)mk);
        int4 tB = __ldg((const int4*)(tg + 1020));
        int4 mB = __ldg((const int4*)(mk + 1020));
        int4 tBl = __ldg((const int4*)(tg + 1016));

        prevF = tc.x;
        score = __ldg(startv + tc.x) + __ldg(pe + tc.x);
        cnt = mc.x ? 1 : 0;

        STEPF(1, tc.y, mc.y, false, false);
        STEPB(1023, tB.w, tB.z, mB.w, false, true, false);
        __syncwarp();
        STEPF(2, tc.z, mc.z, false, false);
        STEPB(1022, tB.z, tB.y, mB.z, false, false, false);
        __syncwarp();
        STEPF(3, tc.w, mc.w, false, true);
        STEPB(1021, tB.y, tB.x, mB.y, false, false, false);
        __syncwarp();
        STEPB(1020, tB.x, tBl.w, mB.x, true, false, false);
        __syncwarp();
        tBcur = tBl;
    }

    #pragma unroll 1
    for (int cc = 1; cc < 128; cc++) {
        int cb = 255 - cc;
        int4 tc = __ldg((const int4*)(tg + 4 * cc));
        int4 mc = __ldg((const int4*)(mk + 4 * cc));
        int4 tB = tBcur;
        int4 mB = __ldg((const int4*)(mk + 4 * cb));
        int4 tBl = __ldg((const int4*)(tg + 4 * cb - 4));
        int tf = 4 * cc;
        int tb3 = 4 * cb + 3;
        bool lastB = (cc == 127);

        STEPF(tf + 0, tc.x, mc.x, true, false);
        STEPB(tb3, tB.w, tB.z, mB.w, false, true, false);
        __syncwarp();
        STEPF(tf + 1, tc.y, mc.y, false, false);
        STEPB(tb3 - 1, tB.z, tB.y, mB.z, false, false, false);
        __syncwarp();
        STEPF(tf + 2, tc.z, mc.z, false, false);
        STEPB(tb3 - 2, tB.y, tB.x, mB.y, false, false, false);
        __syncwarp();
        STEPF(tf + 3, tc.w, mc.w, false, true);
        STEPB(tb3 - 3, tB.x, tBl.w, mB.x, true, false, lastB);
        __syncwarp();
        tBcur = tBl;
    }

    // Z = alpha_511 . beta_511   (scales tracked in logZf/logZb)
    float v = newvF * newvB;   // inactive lanes: 0*0
    #pragma unroll
    for (int off = 16; off > 0; off >>= 1) v += __shfl_xor_sync(FULLM, v, off);
    float denom = logZf + logZb + __logf(v);

    int li = cnt > 0 ? cnt - 1 : 0;
    score += __ldg(endv + __ldg(tg + li));

    if (lane == 0) { s_s[w] = (double)(score - denom); s_c[w] = (double)cnt; }
    __syncthreads();

    if (tid == 0) {
        g_ps[blockIdx.x] = s_s[0] + s_s[1] + s_s[2] + s_s[3];
        g_pc[blockIdx.x] = s_c[0] + s_c[1] + s_c[2] + s_c[3];
        __threadfence();
        unsigned d = atomicAdd(&g_ctr, 1u);
        s_last = (d == gridDim.x - 1) ? 1 : 0;
    }
    __syncthreads();

    if (s_last) {
        // 128 threads reduce 256 partials
        double ls = g_ps[tid] + g_ps[tid + 128];
        double lc = g_pc[tid] + g_pc[tid + 128];
        #pragma unroll
        for (int off = 16; off > 0; off >>= 1) {
            ls += __shfl_xor_sync(FULLM, ls, off);
            lc += __shfl_xor_sync(FULLM, lc, off);
        }
        if (lane == 0) { s_s[w] = ls; s_c[w] = lc; }
        __syncthreads();
        if (tid == 0) {
            double S = s_s[0] + s_s[1] + s_s[2] + s_s[3];
            double C = s_c[0] + s_c[1] + s_c[2] + s_c[3];
            out[0] = (float)(S / C);
            atomicExch(&g_ctr, 0u);   // self-reset for next graph replay
        }
    }
}

extern "C" void kernel_launch(void* const* d_in, const int* in_sizes, int n_in,
                              void* d_out, int out_size) {
    const float* em     = (const float*)d_in[0];
    const int* tags     = (const int*)d_in[1];
    const int* mask     = (const int*)d_in[2];
    const float* startv = (const float*)d_in[3];
    const float* endv   = (const float*)d_in[4];
    const float* trans  = (const float*)d_in[5];

    crf_k<<<B_N / 4, 128>>>(em, tags, mask, startv, endv, trans, (float*)d_out);
}

// round 11
// speedup vs baseline: 2.1986x; 1.4080x over previous
#include <cuda_runtime.h>

#define FULLM 0xffffffffu
#define B_N 1024
#define L_N 1024
#define T_N 21

typedef unsigned long long ull;

__device__ double g_ps[512];
__device__ double g_pc[512];
__device__ unsigned int g_ctr;   // static zero-init; self-resetting

__device__ __forceinline__ ull pk2(float lo, float hi) {
    ull r; asm("mov.b64 %0, {%1, %2};" : "=l"(r) : "f"(lo), "f"(hi)); return r;
}
__device__ __forceinline__ void fma2(ull& a, ull x, ull y) {
    asm("fma.rn.f32x2 %0, %1, %2, %0;" : "+l"(a) : "l"(x), "l"(y));
}
__device__ __forceinline__ ull add2(ull x, ull y) {
    ull r; asm("add.rn.f32x2 %0, %1, %2;" : "=l"(r) : "l"(x), "l"(y)); return r;
}
__device__ __forceinline__ void unpk(ull v, float& lo, float& hi) {
    asm("mov.b64 {%0, %1}, %2;" : "=f"(lo), "=f"(hi) : "l"(v));
}

// 128-thr blocks, 4 warps, TWO sequences per block.
// Warp 2p   = forward  half of sequence p (t=0..511)
// Warp 2p+1 = backward half of sequence p (t=1023..512)
// Doubles resident warps vs R10 (grid 512) while keeping the halved chain.
__global__ __launch_bounds__(128) void crf_k(
    const float* __restrict__ em, const int* __restrict__ tags,
    const int* __restrict__ mask,
    const float* __restrict__ startv, const float* __restrict__ endv,
    const float* __restrict__ transv,
    float* __restrict__ out)
{
    __shared__ ulonglong2 abuf[4][2][8];   // [warp][parity][32 floats]
    __shared__ float s_af[2][32];          // alpha_511 from fwd warp
    __shared__ float s_lZ[2], s_sc[2];
    __shared__ int   s_cn[2];
    __shared__ double s_s[2], s_c[2];
    __shared__ int s_last;

    int tid = threadIdx.x;
    int lane = tid & 31;
    int w = tid >> 5;
    int pair = w >> 1;
    int isB = w & 1;
    int seq = blockIdx.x * 2 + pair;
    bool act = lane < T_N;
    int j = act ? lane : (T_N - 1);

    // fwd warps need column 'lane' of E=exp(trans); bwd warps need row 'lane'.
    ull eM[12];
    {
        float c[24];
        #pragma unroll
        for (int s = 0; s < 24; s++) {
            if (s < T_N && act)
                c[s] = __expf(isB ? __ldg(transv + lane * T_N + s)
                                  : __ldg(transv + s * T_N + lane));
            else c[s] = 0.f;
        }
        #pragma unroll
        for (int m = 0; m < 12; m++) eM[m] = pk2(c[2*m], c[2*m+1]);
    }

    const float* pe = em + (size_t)seq * (L_N * T_N);
    const int* tg = tags + (size_t)seq * L_N;
    const int* mk = mask + (size_t)seq * L_N;

    ulonglong2 (*bf)[8] = abuf[w];

    float score = 0.f, logZ = 0.f, inv = 1.f, lg = 0.f;
    int cnt = 0;
    float newv;

    if (!isB) {
        // ================= FORWARD: t = 0 .. 511 =================
        float em0 = __ldg(pe + j);
        newv = act ? __expf(__ldg(startv + j) + em0) : 0.f;
        ((float*)bf[0])[lane] = newv;

        float eb[8];
        #pragma unroll
        for (int k = 0; k < 8; k++) eb[k] = __ldg(pe + (size_t)(1 + k) * T_N + j);
        __syncwarp();

        int prevF;
        auto STEPF = [&](int t, int ct, int m, bool do_rn, bool prep_rn) {
            float cur = eb[(t - 1) & 7];
            eb[(t - 1) & 7] = __ldg(pe + (size_t)(t + 8) * T_N + j);   // <= 519
            float p = __expf(cur);
            const ulonglong2* rb = bf[(t - 1) & 1];
            ulonglong2 q0 = rb[0], q1 = rb[1], q2 = rb[2], q3 = rb[3], q4 = rb[4], q5 = rb[5];
            if (prep_rn) { float z0, z1; unpk(q0.x, z0, z1); inv = __fdividef(1.f, z0); lg = __logf(z0); }
            ull a0 = 0ull, a1 = 0ull, a2 = 0ull;
            fma2(a0, q0.x, eM[0]);  fma2(a1, q0.y, eM[1]);
            fma2(a2, q1.x, eM[2]);  fma2(a0, q1.y, eM[3]);
            fma2(a1, q2.x, eM[4]);  fma2(a2, q2.y, eM[5]);
            fma2(a0, q3.x, eM[6]);  fma2(a1, q3.y, eM[7]);
            fma2(a2, q4.x, eM[8]);  fma2(a0, q4.y, eM[9]);
            fma2(a1, q5.x, eM[10]); fma2(a2, q5.y, eM[11]);
            ull at = add2(add2(a0, a1), a2);
            float lo, hi; unpk(at, lo, hi);
            float nxt = (lo + hi) * p;
            float ltr = __ldg(transv + prevF * T_N + ct);
            float emt = __ldg(pe + (size_t)t * T_N + ct);
            score += m ? (ltr + emt) : 0.f;
            cnt += m;
            newv = m ? nxt : newv;
            if (do_rn) { newv *= inv; logZ += lg; }
            ((float*)bf[t & 1])[lane] = newv;
            __syncwarp();
            prevF = ct;
        };

        {
            int4 tc = __ldg((const int4*)tg);
            int4 mc = __ldg((const int4*)mk);
            prevF = tc.x;
            score = __ldg(startv + tc.x) + __ldg(pe + tc.x);
            cnt = mc.x ? 1 : 0;
            STEPF(1, tc.y, mc.y, false, false);
            STEPF(2, tc.z, mc.z, false, false);
            STEPF(3, tc.w, mc.w, false, true);
        }
        #pragma unroll 1
        for (int cc = 1; cc < 128; cc++) {
            int4 tc = __ldg((const int4*)(tg + 4 * cc));
            int4 mc = __ldg((const int4*)(mk + 4 * cc));
            int tf = 4 * cc;
            STEPF(tf + 0, tc.x, mc.x, true, false);
            STEPF(tf + 1, tc.y, mc.y, false, false);
            STEPF(tf + 2, tc.z, mc.z, false, false);
            STEPF(tf + 3, tc.w, mc.w, false, true);
        }

        // publish alpha + scalars
        s_af[pair][lane] = newv;
        if (lane == 0) { s_lZ[pair] = logZ; s_sc[pair] = score; s_cn[pair] = cnt; }
    } else {
        // ================= BACKWARD: t = 1023 .. 512 =================
        newv = act ? __expf(__ldg(endv + j)) : 0.f;  // beta_1023
        {
            float e1023 = __ldg(pe + (size_t)1023 * T_N + j);
            ((float*)bf[1])[lane] = __expf(e1023) * newv;
        }
        float eb[8];
        #pragma unroll
        for (int k = 0; k < 8; k++) {
            int r = 1015 + k;
            eb[r & 7] = __ldg(pe + (size_t)r * T_N + j);
        }
        __syncwarp();

        auto STEPB = [&](int t, int ct, int ctm1, int m, bool do_rn, bool prep_rn, bool last) {
            const ulonglong2* rb = bf[t & 1];
            ulonglong2 q0 = rb[0], q1 = rb[1], q2 = rb[2], q3 = rb[3], q4 = rb[4], q5 = rb[5];
            if (prep_rn) { float z0, z1; unpk(q0.x, z0, z1); inv = __fdividef(1.f, z0); lg = __logf(z0); }
            ull a0 = 0ull, a1 = 0ull, a2 = 0ull;
            fma2(a0, q0.x, eM[0]);  fma2(a1, q0.y, eM[1]);
            fma2(a2, q1.x, eM[2]);  fma2(a0, q1.y, eM[3]);
            fma2(a1, q2.x, eM[4]);  fma2(a2, q2.y, eM[5]);
            fma2(a0, q3.x, eM[6]);  fma2(a1, q3.y, eM[7]);
            fma2(a2, q4.x, eM[8]);  fma2(a0, q4.y, eM[9]);
            fma2(a1, q5.x, eM[10]); fma2(a2, q5.y, eM[11]);
            ull at = add2(add2(a0, a1), a2);
            float lo, hi; unpk(at, lo, hi);
            float dotB = lo + hi;
            float ltr = __ldg(transv + ctm1 * T_N + ct);
            float emt = __ldg(pe + (size_t)t * T_N + ct);
            score += m ? (ltr + emt) : 0.f;
            cnt += m;
            newv = m ? dotB : newv;
            if (do_rn) { newv *= inv; logZ += lg; }
            if (!last) {
                float e = eb[(t - 1) & 7];
                eb[(t - 1) & 7] = __ldg(pe + (size_t)(t - 9) * T_N + j);  // >= 503
                ((float*)bf[(t - 1) & 1])[lane] = __expf(e) * newv;
            }
            __syncwarp();
        };

        int4 tBcur;
        {   // chunk 255: t = 1023..1020
            int4 tB  = __ldg((const int4*)(tg + 1020));
            int4 mB  = __ldg((const int4*)(mk + 1020));
            int4 tBl = __ldg((const int4*)(tg + 1016));
            STEPB(1023, tB.w, tB.z, mB.w, false, true,  false);
            STEPB(1022, tB.z, tB.y, mB.z, false, false, false);
            STEPB(1021, tB.y, tB.x, mB.y, false, false, false);
            STEPB(1020, tB.x, tBl.w, mB.x, true, false, false);
            tBcur = tBl;
        }
        #pragma unroll 1
        for (int cb = 254; cb >= 128; cb--) {
            int4 tB  = tBcur;
            int4 mB  = __ldg((const int4*)(mk + 4 * cb));
            int4 tBl = __ldg((const int4*)(tg + 4 * cb - 4));
            int tb3 = 4 * cb + 3;
            bool lastB = (cb == 128);
            STEPB(tb3,     tB.w, tB.z,  mB.w, false, true,  false);
            STEPB(tb3 - 1, tB.z, tB.y,  mB.z, false, false, false);
            STEPB(tb3 - 2, tB.y, tB.x,  mB.y, false, false, false);
            STEPB(tb3 - 3, tB.x, tBl.w, mB.x, true,  false, lastB);
            tBcur = tBl;
        }
    }

    __syncthreads();

    if (isB) {
        // combine: Z = alpha_511 . beta_511
        float v = s_af[pair][lane] * newv;
        #pragma unroll
        for (int off = 16; off > 0; off >>= 1) v += __shfl_xor_sync(FULLM, v, off);
        float denom = s_lZ[pair] + logZ + __logf(v);
        int cntT = s_cn[pair] + cnt;
        float scoreT = s_sc[pair] + score;
        int li = cntT > 0 ? cntT - 1 : 0;
        scoreT += __ldg(endv + __ldg(tg + li));
        if (lane == 0) { s_s[pair] = (double)(scoreT - denom); s_c[pair] = (double)cntT; }
    }
    __syncthreads();

    if (tid == 0) {
        g_ps[blockIdx.x] = s_s[0] + s_s[1];
        g_pc[blockIdx.x] = s_c[0] + s_c[1];
        __threadfence();
        unsigned d = atomicAdd(&g_ctr, 1u);
        s_last = (d == gridDim.x - 1) ? 1 : 0;
    }
    __syncthreads();

    if (s_last) {
        double ls = g_ps[tid] + g_ps[tid + 128] + g_ps[tid + 256] + g_ps[tid + 384];
        double lc = g_pc[tid] + g_pc[tid + 128] + g_pc[tid + 256] + g_pc[tid + 384];
        #pragma unroll
        for (int off = 16; off > 0; off >>= 1) {
            ls += __shfl_xor_sync(FULLM, ls, off);
            lc += __shfl_xor_sync(FULLM, lc, off);
        }
        if (lane == 0) { s_s[w >> 1] = 0.0; }   // ensure defined
        __syncthreads();
        __shared__ double r_s[4], r_c[4];
        if (lane == 0) { r_s[w] = ls; r_c[w] = lc; }
        __syncthreads();
        if (tid == 0) {
            double S = r_s[0] + r_s[1] + r_s[2] + r_s[3];
            double C = r_c[0] + r_c[1] + r_c[2] + r_c[3];
            out[0] = (float)(S / C);
            atomicExch(&g_ctr, 0u);   // self-reset for next graph replay
        }
    }
}

extern "C" void kernel_launch(void* const* d_in, const int* in_sizes, int n_in,
                              void* d_out, int out_size) {
    const float* em     = (const float*)d_in[0];
    const int* tags     = (const int*)d_in[1];
    const int* mask     = (const int*)d_in[2];
    const float* startv = (const float*)d_in[3];
    const float* endv   = (const float*)d_in[4];
    const float* trans  = (const float*)d_in[5];

    crf_k<<<B_N / 2, 128>>>(em, tags, mask, startv, endv, trans, (float*)d_out);
}

// round 12
// speedup vs baseline: 3.6321x; 1.6520x over previous
#include <cuda_runtime.h>

#define FULLM 0xffffffffu
#define B_N 1024
#define L_N 1024
#define T_N 21

typedef unsigned long long ull;

__device__ double g_ps[512];
__device__ double g_pc[512];
__device__ unsigned int g_ctr;   // static zero-init; self-resetting

__device__ __forceinline__ ull pk2(float lo, float hi) {
    ull r; asm("mov.b64 %0, {%1, %2};" : "=l"(r) : "f"(lo), "f"(hi)); return r;
}
__device__ __forceinline__ void fma2(ull& a, ull x, ull y) {
    asm("fma.rn.f32x2 %0, %1, %2, %0;" : "+l"(a) : "l"(x), "l"(y));
}
__device__ __forceinline__ ull add2(ull x, ull y) {
    ull r; asm("add.rn.f32x2 %0, %1, %2;" : "=l"(r) : "l"(x), "l"(y)); return r;
}
__device__ __forceinline__ void unpk(ull v, float& lo, float& hi) {
    asm("mov.b64 {%0, %1}, %2;" : "=f"(lo), "=f"(hi) : "l"(v));
}

// 128-thr blocks, 4 warps, two sequences per block: warp 2p = forward half
// (t=0..511), warp 2p+1 = backward half (t=1023..512) of sequence p.
// Mainloops are 8-step unrolled blocks with LITERAL slot indices so the
// emission pipeline eb[8] stays in registers (runtime (t-1)&7 indexing was
// demoting it to local memory -> LDL/STL on the critical path).
__global__ __launch_bounds__(128) void crf_k(
    const float* __restrict__ em, const int* __restrict__ tags,
    const int* __restrict__ mask,
    const float* __restrict__ startv, const float* __restrict__ endv,
    const float* __restrict__ transv,
    float* __restrict__ out)
{
    __shared__ ulonglong2 abuf[4][2][8];   // [warp][parity][32 floats]
    __shared__ float s_af[2][32];
    __shared__ float s_lZ[2], s_sc[2];
    __shared__ int   s_cn[2];
    __shared__ double s_s[2], s_c[2];
    __shared__ double r_s[4], r_c[4];
    __shared__ int s_last;

    int tid = threadIdx.x;
    int lane = tid & 31;
    int w = tid >> 5;
    int pair = w >> 1;
    int isB = w & 1;
    int seq = blockIdx.x * 2 + pair;
    bool act = lane < T_N;
    int j = act ? lane : (T_N - 1);

    // fwd warps: column 'lane' of E=exp(trans); bwd warps: row 'lane'.
    ull eM[12];
    {
        float c[24];
        #pragma unroll
        for (int s = 0; s < 24; s++) {
            if (s < T_N && act)
                c[s] = __expf(isB ? __ldg(transv + lane * T_N + s)
                                  : __ldg(transv + s * T_N + lane));
            else c[s] = 0.f;
        }
        #pragma unroll
        for (int m = 0; m < 12; m++) eM[m] = pk2(c[2*m], c[2*m+1]);
    }

    const float* pe = em + (size_t)seq * (L_N * T_N);
    const int* tg = tags + (size_t)seq * L_N;
    const int* mk = mask + (size_t)seq * L_N;

    ulonglong2 (*bf)[8] = abuf[w];

    float score = 0.f, logZ = 0.f, inv = 1.f, lg = 0.f;
    int cnt = 0;
    float newv;
    float eb[8];

    if (!isB) {
        // ================= FORWARD: t = 0 .. 511 =================
        float em0 = __ldg(pe + j);
        newv = act ? __expf(__ldg(startv + j) + em0) : 0.f;
        ((float*)bf[0])[lane] = newv;

        #pragma unroll
        for (int k = 1; k <= 8; k++) eb[k & 7] = __ldg(pe + k * T_N + j);
        __syncwarp();

        int prevF;
        // slot = t&7 (literal at every call site)
        auto STEPF = [&](const float* pb, int slot, int ct, int m, bool do_rn, bool prep_rn) {
            float cur = eb[slot];
            eb[slot] = __ldg(pb + (slot + 8) * T_N + j);   // row t+8 <= 519
            float p = __expf(cur);
            const ulonglong2* rb = bf[(slot + 1) & 1];
            ulonglong2 q0 = rb[0], q1 = rb[1], q2 = rb[2], q3 = rb[3], q4 = rb[4], q5 = rb[5];
            if (prep_rn) { float z0, z1; unpk(q0.x, z0, z1); inv = __fdividef(1.f, z0); lg = __logf(z0); }
            ull a0 = 0ull, a1 = 0ull, a2 = 0ull;
            fma2(a0, q0.x, eM[0]);  fma2(a1, q0.y, eM[1]);
            fma2(a2, q1.x, eM[2]);  fma2(a0, q1.y, eM[3]);
            fma2(a1, q2.x, eM[4]);  fma2(a2, q2.y, eM[5]);
            fma2(a0, q3.x, eM[6]);  fma2(a1, q3.y, eM[7]);
            fma2(a2, q4.x, eM[8]);  fma2(a0, q4.y, eM[9]);
            fma2(a1, q5.x, eM[10]); fma2(a2, q5.y, eM[11]);
            ull at = add2(add2(a0, a1), a2);
            float lo, hi; unpk(at, lo, hi);
            float nxt = (lo + hi) * p;
            float ltr = __ldg(transv + prevF * T_N + ct);
            float emt = __ldg(pb + slot * T_N + ct);     // row t
            score += m ? (ltr + emt) : 0.f;
            cnt += m;
            newv = m ? nxt : newv;
            if (do_rn) { newv *= inv; logZ += lg; }
            ((float*)bf[slot & 1])[lane] = newv;
            __syncwarp();
            prevF = ct;
        };

        {   // prologue: t = 1..7
            int4 t0 = __ldg((const int4*)tg);
            int4 m0 = __ldg((const int4*)mk);
            int4 t1 = __ldg((const int4*)(tg + 4));
            int4 m1 = __ldg((const int4*)(mk + 4));
            prevF = t0.x;
            score = __ldg(startv + t0.x) + __ldg(pe + t0.x);
            cnt = m0.x ? 1 : 0;
            STEPF(pe, 1, t0.y, m0.y, false, false);
            STEPF(pe, 2, t0.z, m0.z, false, false);
            STEPF(pe, 3, t0.w, m0.w, false, true);
            STEPF(pe, 4, t1.x, m1.x, true,  false);
            STEPF(pe, 5, t1.y, m1.y, false, false);
            STEPF(pe, 6, t1.z, m1.z, false, false);
            STEPF(pe, 7, t1.w, m1.w, false, true);
        }
        const float* pb = pe + 8 * T_N;
        const int* tgb = tg + 8;
        const int* mkb = mk + 8;
        #pragma unroll 1
        for (int blk = 1; blk <= 63; blk++) {     // t = 8..511
            int4 tA = __ldg((const int4*)tgb);
            int4 tB = __ldg((const int4*)(tgb + 4));
            int4 mA = __ldg((const int4*)mkb);
            int4 mB = __ldg((const int4*)(mkb + 4));
            STEPF(pb, 0, tA.x, mA.x, true,  false);
            STEPF(pb, 1, tA.y, mA.y, false, false);
            STEPF(pb, 2, tA.z, mA.z, false, false);
            STEPF(pb, 3, tA.w, mA.w, false, true);
            STEPF(pb, 4, tB.x, mB.x, true,  false);
            STEPF(pb, 5, tB.y, mB.y, false, false);
            STEPF(pb, 6, tB.z, mB.z, false, false);
            STEPF(pb, 7, tB.w, mB.w, false, true);
            pb += 8 * T_N; tgb += 8; mkb += 8;
        }

        s_af[pair][lane] = newv;
        if (lane == 0) { s_lZ[pair] = logZ; s_sc[pair] = score; s_cn[pair] = cnt; }
    } else {
        // ================= BACKWARD: t = 1023 .. 512 =================
        newv = act ? __expf(__ldg(endv + j)) : 0.f;   // beta_1023
        ((float*)bf[1])[lane] = __expf(__ldg(pe + (size_t)1023 * T_N + j)) * newv;

        #pragma unroll
        for (int k = 0; k < 8; k++)
            eb[(1015 + k) & 7] = __ldg(pe + (size_t)(1015 + k) * T_N + j);
        __syncwarp();

        // slot = t&7 (literal). pb = pe + tb*T_N, t = tb+slot.
        auto STEPB = [&](const float* pb, int slot, int ct, int ctm1, int m,
                         bool do_rn, bool prep_rn, bool last) {
            const ulonglong2* rb = bf[slot & 1];
            ulonglong2 q0 = rb[0], q1 = rb[1], q2 = rb[2], q3 = rb[3], q4 = rb[4], q5 = rb[5];
            if (prep_rn) { float z0, z1; unpk(q0.x, z0, z1); inv = __fdividef(1.f, z0); lg = __logf(z0); }
            ull a0 = 0ull, a1 = 0ull, a2 = 0ull;
            fma2(a0, q0.x, eM[0]);  fma2(a1, q0.y, eM[1]);
            fma2(a2, q1.x, eM[2]);  fma2(a0, q1.y, eM[3]);
            fma2(a1, q2.x, eM[4]);  fma2(a2, q2.y, eM[5]);
            fma2(a0, q3.x, eM[6]);  fma2(a1, q3.y, eM[7]);
            fma2(a2, q4.x, eM[8]);  fma2(a0, q4.y, eM[9]);
            fma2(a1, q5.x, eM[10]); fma2(a2, q5.y, eM[11]);
            ull at = add2(add2(a0, a1), a2);
            float lo, hi; unpk(at, lo, hi);
            float dotB = lo + hi;
            float ltr = __ldg(transv + ctm1 * T_N + ct);
            float emt = __ldg(pb + slot * T_N + ct);     // row t
            score += m ? (ltr + emt) : 0.f;
            cnt += m;
            newv = m ? dotB : newv;
            if (do_rn) { newv *= inv; logZ += lg; }
            if (!last) {
                float e = eb[(slot + 7) & 7];                     // row t-1
                eb[(slot + 7) & 7] = __ldg(pb + (slot - 9) * T_N + j);  // row t-9
                ((float*)bf[(slot + 1) & 1])[lane] = __expf(e) * newv;
            }
            __syncwarp();
        };

        int4 tU = __ldg((const int4*)(tg + 1020));
        const float* pb = pe + 1016 * T_N;
        const int* tgb = tg + 1016;
        const int* mkb = mk + 1016;
        #pragma unroll 1
        for (int blk = 0; blk < 63; blk++) {      // t = 1023 .. 520
            int4 tL = __ldg((const int4*)tgb);
            int4 tP = __ldg((const int4*)(tgb - 4));
            int4 mU = __ldg((const int4*)(mkb + 4));
            int4 mL = __ldg((const int4*)mkb);
            STEPB(pb, 7, tU.w, tU.z, mU.w, false, true,  false);
            STEPB(pb, 6, tU.z, tU.y, mU.z, false, false, false);
            STEPB(pb, 5, tU.y, tU.x, mU.y, false, false, false);
            STEPB(pb, 4, tU.x, tL.w, mU.x, true,  false, false);
            STEPB(pb, 3, tL.w, tL.z, mL.w, false, true,  false);
            STEPB(pb, 2, tL.z, tL.y, mL.z, false, false, false);
            STEPB(pb, 1, tL.y, tL.x, mL.y, false, false, false);
            STEPB(pb, 0, tL.x, tP.w, mL.x, true,  false, false);
            tU = tP;
            pb -= 8 * T_N; tgb -= 8; mkb -= 8;
        }
        {   // peeled final block: t = 519 .. 512 (tgb == tg+512 here)
            int4 tL = __ldg((const int4*)tgb);
            int4 tP = __ldg((const int4*)(tgb - 4));
            int4 mU = __ldg((const int4*)(mkb + 4));
            int4 mL = __ldg((const int4*)mkb);
            STEPB(pb, 7, tU.w, tU.z, mU.w, false, true,  false);
            STEPB(pb, 6, tU.z, tU.y, mU.z, false, false, false);
            STEPB(pb, 5, tU.y, tU.x, mU.y, false, false, false);
            STEPB(pb, 4, tU.x, tL.w, mU.x, true,  false, false);
            STEPB(pb, 3, tL.w, tL.z, mL.w, false, true,  false);
            STEPB(pb, 2, tL.z, tL.y, mL.z, false, false, false);
            STEPB(pb, 1, tL.y, tL.x, mL.y, false, false, false);
            STEPB(pb, 0, tL.x, tP.w, mL.x, true,  false, true);
        }
    }

    __syncthreads();

    if (isB) {
        // combine: Z = alpha_511 . beta_511
        float v = s_af[pair][lane] * newv;
        #pragma unroll
        for (int off = 16; off > 0; off >>= 1) v += __shfl_xor_sync(FULLM, v, off);
        float denom = s_lZ[pair] + logZ + __logf(v);
        int cntT = s_cn[pair] + cnt;
        float scoreT = s_sc[pair] + score;
        int li = cntT > 0 ? cntT - 1 : 0;
        scoreT += __ldg(endv + __ldg(tg + li));
        if (lane == 0) { s_s[pair] = (double)(scoreT - denom); s_c[pair] = (double)cntT; }
    }
    __syncthreads();

    if (tid == 0) {
        g_ps[blockIdx.x] = s_s[0] + s_s[1];
        g_pc[blockIdx.x] = s_c[0] + s_c[1];
        __threadfence();
        unsigned d = atomicAdd(&g_ctr, 1u);
        s_last = (d == gridDim.x - 1) ? 1 : 0;
    }
    __syncthreads();

    if (s_last) {
        double ls = g_ps[tid] + g_ps[tid + 128] + g_ps[tid + 256] + g_ps[tid + 384];
        double lc = g_pc[tid] + g_pc[tid + 128] + g_pc[tid + 256] + g_pc[tid + 384];
        #pragma unroll
        for (int off = 16; off > 0; off >>= 1) {
            ls += __shfl_xor_sync(FULLM, ls, off);
            lc += __shfl_xor_sync(FULLM, lc, off);
        }
        if (lane == 0) { r_s[w] = ls; r_c[w] = lc; }
        __syncthreads();
        if (tid == 0) {
            double S = r_s[0] + r_s[1] + r_s[2] + r_s[3];
            double C = r_c[0] + r_c[1] + r_c[2] + r_c[3];
            out[0] = (float)(S / C);
            atomicExch(&g_ctr, 0u);   // self-reset for next graph replay
        }
    }
}

extern "C" void kernel_launch(void* const* d_in, const int* in_sizes, int n_in,
                              void* d_out, int out_size) {
    const float* em     = (const float*)d_in[0];
    const int* tags     = (const int*)d_in[1];
    const int* mask     = (const int*)d_in[2];
    const float* startv = (const float*)d_in[3];
    const float* endv   = (const float*)d_in[4];
    const float* trans  = (const float*)d_in[5];

    crf_k<<<B_N / 2, 128>>>(em, tags, mask, startv, endv, trans, (float*)d_out);
}

// round 13
// speedup vs baseline: 4.1968x; 1.1555x over previous
#include <cuda_runtime.h>

#define FULLM 0xffffffffu
#define B_N 1024
#define L_N 1024
#define T_N 21

typedef unsigned long long ull;

__device__ double g_ps[256];
__device__ double g_pc[256];
__device__ unsigned int g_ctr;   // static zero-init; self-resetting

__device__ __forceinline__ ull pk2(float lo, float hi) {
    ull r; asm("mov.b64 %0, {%1, %2};" : "=l"(r) : "f"(lo), "f"(hi)); return r;
}
__device__ __forceinline__ void fma2(ull& a, ull x, ull y) {
    asm("fma.rn.f32x2 %0, %1, %2, %0;" : "+l"(a) : "l"(x), "l"(y));
}
__device__ __forceinline__ ull add2(ull x, ull y) {
    ull r; asm("add.rn.f32x2 %0, %1, %2;" : "=l"(r) : "l"(x), "l"(y)); return r;
}
__device__ __forceinline__ void unpk(ull v, float& lo, float& hi) {
    asm("mov.b64 {%0, %1}, %2;" : "=f"(lo), "=f"(hi) : "l"(v));
}

// 128-thr blocks, 4 warps, FOUR sequences per block (2 pairs).
// warp 2p   = forward  halves (t=0..511)  of seqs {2p, 2p+1}
// warp 2p+1 = backward halves (t=1023..512) of the same two seqs
// Two interleaved chains per warp double per-warp ILP/duty; the numerator
// (score/cnt) is computed in a bulk lane-parallel phase, not in the loop.
__global__ __launch_bounds__(128) void crf_k(
    const float* __restrict__ em, const int* __restrict__ tags,
    const int* __restrict__ mask,
    const float* __restrict__ startv, const float* __restrict__ endv,
    const float* __restrict__ transv,
    float* __restrict__ out)
{
    __shared__ ulonglong2 abuf[4][2][2][8];  // [warp][chain][parity][32 floats]
    __shared__ float s_af[2][2][32];
    __shared__ float s_lZ[2][2], s_sc[2][2];
    __shared__ int   s_cn[2][2];
    __shared__ double s_s[2], s_c[2];
    __shared__ double r_s[4], r_c[4];
    __shared__ int s_last;

    int tid = threadIdx.x;
    int lane = tid & 31;
    int w = tid >> 5;
    int pair = w >> 1;
    int isB = w & 1;
    int s0 = blockIdx.x * 4 + pair * 2;
    bool act = lane < T_N;
    int j = act ? lane : (T_N - 1);

    // fwd warps: column 'lane' of E=exp(trans); bwd warps: row 'lane'.
    ull eM[12];
    {
        float c[24];
        #pragma unroll
        for (int s = 0; s < 24; s++) {
            if (s < T_N && act)
                c[s] = __expf(isB ? __ldg(transv + lane * T_N + s)
                                  : __ldg(transv + s * T_N + lane));
            else c[s] = 0.f;
        }
        #pragma unroll
        for (int m = 0; m < 12; m++) eM[m] = pk2(c[2*m], c[2*m+1]);
    }

    const float* pe0 = em + (size_t)s0 * (L_N * T_N);
    const float* pe1 = pe0 + (size_t)(L_N * T_N);
    const int* tg0 = tags + (size_t)s0 * L_N;
    const int* tg1 = tg0 + L_N;
    const int* mk0 = mask + (size_t)s0 * L_N;
    const int* mk1 = mk0 + L_N;

    // ================= bulk numerator: fwd sums t=1..511 (+t0 term), bwd t=512..1023 =================
    float num[2]; int cnum[2];
    #pragma unroll
    for (int q = 0; q < 2; q++) {
        const int* tgq = q ? tg1 : tg0;
        const int* mkq = q ? mk1 : mk0;
        const float* peq = q ? pe1 : pe0;
        float acc = 0.f; int c = 0;
        int base = isB ? 512 : 1;
        #pragma unroll 1
        for (int k = 0; k < 16; k++) {
            int t = base + k * 32 + lane;
            if (isB || t <= 511) {
                int ct = __ldg(tgq + t);
                int pt = __ldg(tgq + t - 1);
                int m  = __ldg(mkq + t);
                float ev = __ldg(peq + t * T_N + ct);
                float tv = __ldg(transv + pt * T_N + ct);
                acc += m ? (ev + tv) : 0.f;
                c += m;
            }
        }
        #pragma unroll
        for (int off = 16; off > 0; off >>= 1) {
            acc += __shfl_xor_sync(FULLM, acc, off);
            c   += __shfl_xor_sync(FULLM, c, off);
        }
        if (!isB) {
            int t0t = __ldg(tgq);
            acc += __ldg(startv + t0t) + __ldg(peq + t0t);
            c += __ldg(mkq) ? 1 : 0;
        }
        num[q] = acc; cnum[q] = c;
    }

    // ================= recursion: two chains per warp =================
    ulonglong2 (*bf0)[8] = abuf[w][0];
    ulonglong2 (*bf1)[8] = abuf[w][1];
    float lZ0 = 0.f, lZ1 = 0.f, inv0 = 1.f, lg0 = 0.f, inv1 = 1.f, lg1 = 0.f;
    float nv0, nv1;
    float eA[8], eB[8];

    if (!isB) {
        // -------- FORWARD both seqs: t = 0..511 --------
        nv0 = act ? __expf(__ldg(startv + j) + __ldg(pe0 + j)) : 0.f;
        nv1 = act ? __expf(__ldg(startv + j) + __ldg(pe1 + j)) : 0.f;
        ((float*)bf0[0])[lane] = nv0;
        ((float*)bf1[0])[lane] = nv1;
        #pragma unroll
        for (int k = 1; k <= 8; k++) {
            eA[k & 7] = __ldg(pe0 + k * T_N + j);
            eB[k & 7] = __ldg(pe1 + k * T_N + j);
        }
        __syncwarp();

        auto STEPF = [&](const float* pb0, const float* pb1, int slot,
                         int m0, int m1, bool do_rn, bool prep_rn) {
            float c0 = eA[slot]; eA[slot] = __ldg(pb0 + (slot + 8) * T_N + j);
            float c1 = eB[slot]; eB[slot] = __ldg(pb1 + (slot + 8) * T_N + j);
            float p0 = __expf(c0), p1 = __expf(c1);
            const ulonglong2* rA = bf0[(slot + 1) & 1];
            const ulonglong2* rB = bf1[(slot + 1) & 1];
            ulonglong2 qa0 = rA[0], qa1 = rA[1], qa2 = rA[2], qa3 = rA[3], qa4 = rA[4], qa5 = rA[5];
            ulonglong2 qb0 = rB[0], qb1 = rB[1], qb2 = rB[2], qb3 = rB[3], qb4 = rB[4], qb5 = rB[5];
            if (prep_rn) {
                float z, zz;
                unpk(qa0.x, z, zz); inv0 = __fdividef(1.f, z); lg0 = __logf(z);
                unpk(qb0.x, z, zz); inv1 = __fdividef(1.f, z); lg1 = __logf(z);
            }
            ull a0 = 0ull, a1 = 0ull, a2 = 0ull, b0 = 0ull, b1 = 0ull, b2 = 0ull;
            fma2(a0, qa0.x, eM[0]);  fma2(b0, qb0.x, eM[0]);
            fma2(a1, qa0.y, eM[1]);  fma2(b1, qb0.y, eM[1]);
            fma2(a2, qa1.x, eM[2]);  fma2(b2, qb1.x, eM[2]);
            fma2(a0, qa1.y, eM[3]);  fma2(b0, qb1.y, eM[3]);
            fma2(a1, qa2.x, eM[4]);  fma2(b1, qb2.x, eM[4]);
            fma2(a2, qa2.y, eM[5]);  fma2(b2, qb2.y, eM[5]);
            fma2(a0, qa3.x, eM[6]);  fma2(b0, qb3.x, eM[6]);
            fma2(a1, qa3.y, eM[7]);  fma2(b1, qb3.y, eM[7]);
            fma2(a2, qa4.x, eM[8]);  fma2(b2, qb4.x, eM[8]);
            fma2(a0, qa4.y, eM[9]);  fma2(b0, qb4.y, eM[9]);
            fma2(a1, qa5.x, eM[10]); fma2(b1, qb5.x, eM[10]);
            fma2(a2, qa5.y, eM[11]); fma2(b2, qb5.y, eM[11]);
            ull atA = add2(add2(a0, a1), a2);
            ull atB = add2(add2(b0, b1), b2);
            float lo, hi;
            unpk(atA, lo, hi); float nx0 = (lo + hi) * p0;
            unpk(atB, lo, hi); float nx1 = (lo + hi) * p1;
            nv0 = m0 ? nx0 : nv0;
            nv1 = m1 ? nx1 : nv1;
            if (do_rn) { nv0 *= inv0; lZ0 += lg0; nv1 *= inv1; lZ1 += lg1; }
            ((float*)bf0[slot & 1])[lane] = nv0;
            ((float*)bf1[slot & 1])[lane] = nv1;
            __syncwarp();
        };

        {   // prologue t=1..7
            int4 xa0 = __ldg((const int4*)mk0), xa1 = __ldg((const int4*)(mk0 + 4));
            int4 xb0 = __ldg((const int4*)mk1), xb1 = __ldg((const int4*)(mk1 + 4));
            STEPF(pe0, pe1, 1, xa0.y, xb0.y, false, false);
            STEPF(pe0, pe1, 2, xa0.z, xb0.z, false, false);
            STEPF(pe0, pe1, 3, xa0.w, xb0.w, false, true);
            STEPF(pe0, pe1, 4, xa1.x, xb1.x, true,  false);
            STEPF(pe0, pe1, 5, xa1.y, xb1.y, false, false);
            STEPF(pe0, pe1, 6, xa1.z, xb1.z, false, false);
            STEPF(pe0, pe1, 7, xa1.w, xb1.w, false, true);
        }
        const float* pb0 = pe0 + 8 * T_N;
        const float* pb1 = pe1 + 8 * T_N;
        const int* mka = mk0 + 8;
        const int* mkb = mk1 + 8;
        #pragma unroll 1
        for (int blk = 1; blk <= 63; blk++) {   // t = 8..511
            int4 xa0 = __ldg((const int4*)mka), xa1 = __ldg((const int4*)(mka + 4));
            int4 xb0 = __ldg((const int4*)mkb), xb1 = __ldg((const int4*)(mkb + 4));
            STEPF(pb0, pb1, 0, xa0.x, xb0.x, true,  false);
            STEPF(pb0, pb1, 1, xa0.y, xb0.y, false, false);
            STEPF(pb0, pb1, 2, xa0.z, xb0.z, false, false);
            STEPF(pb0, pb1, 3, xa0.w, xb0.w, false, true);
            STEPF(pb0, pb1, 4, xa1.x, xb1.x, true,  false);
            STEPF(pb0, pb1, 5, xa1.y, xb1.y, false, false);
            STEPF(pb0, pb1, 6, xa1.z, xb1.z, false, false);
            STEPF(pb0, pb1, 7, xa1.w, xb1.w, false, true);
            pb0 += 8 * T_N; pb1 += 8 * T_N; mka += 8; mkb += 8;
        }

        s_af[pair][0][lane] = nv0;
        s_af[pair][1][lane] = nv1;
        if (lane == 0) {
            s_lZ[pair][0] = lZ0; s_lZ[pair][1] = lZ1;
            s_sc[pair][0] = num[0]; s_sc[pair][1] = num[1];
            s_cn[pair][0] = cnum[0]; s_cn[pair][1] = cnum[1];
        }
    } else {
        // -------- BACKWARD both seqs: t = 1023..512 --------
        float e0 = act ? __expf(__ldg(endv + j)) : 0.f;
        nv0 = e0; nv1 = e0;
        ((float*)bf0[1])[lane] = __expf(__ldg(pe0 + (size_t)1023 * T_N + j)) * nv0;
        ((float*)bf1[1])[lane] = __expf(__ldg(pe1 + (size_t)1023 * T_N + j)) * nv1;
        #pragma unroll
        for (int k = 0; k < 8; k++) {
            eA[(1015 + k) & 7] = __ldg(pe0 + (size_t)(1015 + k) * T_N + j);
            eB[(1015 + k) & 7] = __ldg(pe1 + (size_t)(1015 + k) * T_N + j);
        }
        __syncwarp();

        auto STEPB = [&](const float* pb0, const float* pb1, int slot,
                         int m0, int m1, bool do_rn, bool prep_rn, bool last) {
            const ulonglong2* rA = bf0[slot & 1];
            const ulonglong2* rB = bf1[slot & 1];
            ulonglong2 qa0 = rA[0], qa1 = rA[1], qa2 = rA[2], qa3 = rA[3], qa4 = rA[4], qa5 = rA[5];
            ulonglong2 qb0 = rB[0], qb1 = rB[1], qb2 = rB[2], qb3 = rB[3], qb4 = rB[4], qb5 = rB[5];
            if (prep_rn) {
                float z, zz;
                unpk(qa0.x, z, zz); inv0 = __fdividef(1.f, z); lg0 = __logf(z);
                unpk(qb0.x, z, zz); inv1 = __fdividef(1.f, z); lg1 = __logf(z);
            }
            ull a0 = 0ull, a1 = 0ull, a2 = 0ull, b0 = 0ull, b1 = 0ull, b2 = 0ull;
            fma2(a0, qa0.x, eM[0]);  fma2(b0, qb0.x, eM[0]);
            fma2(a1, qa0.y, eM[1]);  fma2(b1, qb0.y, eM[1]);
            fma2(a2, qa1.x, eM[2]);  fma2(b2, qb1.x, eM[2]);
            fma2(a0, qa1.y, eM[3]);  fma2(b0, qb1.y, eM[3]);
            fma2(a1, qa2.x, eM[4]);  fma2(b1, qb2.x, eM[4]);
            fma2(a2, qa2.y, eM[5]);  fma2(b2, qb2.y, eM[5]);
            fma2(a0, qa3.x, eM[6]);  fma2(b0, qb3.x, eM[6]);
            fma2(a1, qa3.y, eM[7]);  fma2(b1, qb3.y, eM[7]);
            fma2(a2, qa4.x, eM[8]);  fma2(b2, qb4.x, eM[8]);
            fma2(a0, qa4.y, eM[9]);  fma2(b0, qb4.y, eM[9]);
            fma2(a1, qa5.x, eM[10]); fma2(b1, qb5.x, eM[10]);
            fma2(a2, qa5.y, eM[11]); fma2(b2, qb5.y, eM[11]);
            ull atA = add2(add2(a0, a1), a2);
            ull atB = add2(add2(b0, b1), b2);
            float lo, hi;
            unpk(atA, lo, hi); float d0 = lo + hi;
            unpk(atB, lo, hi); float d1 = lo + hi;
            nv0 = m0 ? d0 : nv0;
            nv1 = m1 ? d1 : nv1;
            if (do_rn) { nv0 *= inv0; lZ0 += lg0; nv1 *= inv1; lZ1 += lg1; }
            if (!last) {
                float ea = eA[(slot + 7) & 7];
                eA[(slot + 7) & 7] = __ldg(pb0 + (slot - 9) * T_N + j);
                float eb2 = eB[(slot + 7) & 7];
                eB[(slot + 7) & 7] = __ldg(pb1 + (slot - 9) * T_N + j);
                ((float*)bf0[(slot + 1) & 1])[lane] = __expf(ea) * nv0;
                ((float*)bf1[(slot + 1) & 1])[lane] = __expf(eb2) * nv1;
            }
            __syncwarp();
        };

        const float* pb0 = pe0 + 1016 * T_N;
        const float* pb1 = pe1 + 1016 * T_N;
        const int* mka = mk0 + 1016;
        const int* mkb = mk1 + 1016;
        #pragma unroll 1
        for (int blk = 0; blk < 63; blk++) {    // t = 1023 .. 520
            int4 ua = __ldg((const int4*)(mka + 4)), la = __ldg((const int4*)mka);
            int4 ub = __ldg((const int4*)(mkb + 4)), lb = __ldg((const int4*)mkb);
            STEPB(pb0, pb1, 7, ua.w, ub.w, false, true,  false);
            STEPB(pb0, pb1, 6, ua.z, ub.z, false, false, false);
            STEPB(pb0, pb1, 5, ua.y, ub.y, false, false, false);
            STEPB(pb0, pb1, 4, ua.x, ub.x, true,  false, false);
            STEPB(pb0, pb1, 3, la.w, lb.w, false, true,  false);
            STEPB(pb0, pb1, 2, la.z, lb.z, false, false, false);
            STEPB(pb0, pb1, 1, la.y, lb.y, false, false, false);
            STEPB(pb0, pb1, 0, la.x, lb.x, true,  false, false);
            pb0 -= 8 * T_N; pb1 -= 8 * T_N; mka -= 8; mkb -= 8;
        }
        {   // peeled final block: t = 519..512
            int4 ua = __ldg((const int4*)(mka + 4)), la = __ldg((const int4*)mka);
            int4 ub = __ldg((const int4*)(mkb + 4)), lb = __ldg((const int4*)mkb);
            STEPB(pb0, pb1, 7, ua.w, ub.w, false, true,  false);
            STEPB(pb0, pb1, 6, ua.z, ub.z, false, false, false);
            STEPB(pb0, pb1, 5, ua.y, ub.y, false, false, false);
            STEPB(pb0, pb1, 4, ua.x, ub.x, true,  false, false);
            STEPB(pb0, pb1, 3, la.w, lb.w, false, true,  false);
            STEPB(pb0, pb1, 2, la.z, lb.z, false, false, false);
            STEPB(pb0, pb1, 1, la.y, lb.y, false, false, false);
            STEPB(pb0, pb1, 0, la.x, lb.x, true,  false, true);
        }
    }

    __syncthreads();

    if (isB) {
        // combine both seqs of the pair: Z = alpha_511 . beta_511
        float v0 = s_af[pair][0][lane] * nv0;
        float v1 = s_af[pair][1][lane] * nv1;
        #pragma unroll
        for (int off = 16; off > 0; off >>= 1) {
            v0 += __shfl_xor_sync(FULLM, v0, off);
            v1 += __shfl_xor_sync(FULLM, v1, off);
        }
        float den0 = s_lZ[pair][0] + lZ0 + __logf(v0);
        float den1 = s_lZ[pair][1] + lZ1 + __logf(v1);
        int cT0 = s_cn[pair][0] + cnum[0];
        int cT1 = s_cn[pair][1] + cnum[1];
        float sc0 = s_sc[pair][0] + num[0];
        float sc1 = s_sc[pair][1] + num[1];
        int li0 = cT0 > 0 ? cT0 - 1 : 0;
        int li1 = cT1 > 0 ? cT1 - 1 : 0;
        sc0 += __ldg(endv + __ldg(tg0 + li0));
        sc1 += __ldg(endv + __ldg(tg1 + li1));
        if (lane == 0) {
            s_s[pair] = (double)(sc0 - den0) + (double)(sc1 - den1);
            s_c[pair] = (double)(cT0 + cT1);
        }
    }
    __syncthreads();

    if (tid == 0) {
        g_ps[blockIdx.x] = s_s[0] + s_s[1];
        g_pc[blockIdx.x] = s_c[0] + s_c[1];
        __threadfence();
        unsigned d = atomicAdd(&g_ctr, 1u);
        s_last = (d == gridDim.x - 1) ? 1 : 0;
    }
    __syncthreads();

    if (s_last) {
        double ls = g_ps[tid] + g_ps[tid + 128];
        double lc = g_pc[tid] + g_pc[tid + 128];
        #pragma unroll
        for (int off = 16; off > 0; off >>= 1) {
            ls += __shfl_xor_sync(FULLM, ls, off);
            lc += __shfl_xor_sync(FULLM, lc, off);
        }
        if (lane == 0) { r_s[w] = ls; r_c[w] = lc; }
        __syncthreads();
        if (tid == 0) {
            double S = r_s[0] + r_s[1] + r_s[2] + r_s[3];
            double C = r_c[0] + r_c[1] + r_c[2] + r_c[3];
            out[0] = (float)(S / C);
            atomicExch(&g_ctr, 0u);   // self-reset for next graph replay
        }
    }
}

extern "C" void kernel_launch(void* const* d_in, const int* in_sizes, int n_in,
                              void* d_out, int out_size) {
    const float* em     = (const float*)d_in[0];
    const int* tags     = (const int*)d_in[1];
    const int* mask     = (const int*)d_in[2];
    const float* startv = (const float*)d_in[3];
    const float* endv   = (const float*)d_in[4];
    const float* trans  = (const float*)d_in[5];

    crf_k<<<B_N / 4, 128>>>(em, tags, mask, startv, endv, trans, (float*)d_out);
}

// round 15
// speedup vs baseline: 4.3936x; 1.0469x over previous
#include <cuda_runtime.h>

#define FULLM 0xffffffffu
#define B_N 1024
#define L_N 1024
#define T_N 21

typedef unsigned long long ull;

__device__ double g_ps[256];
__device__ double g_pc[256];
__device__ unsigned int g_ctr;   // static zero-init; self-resetting

__device__ __forceinline__ ull pk2(float lo, float hi) {
    ull r; asm("mov.b64 %0, {%1, %2};" : "=l"(r) : "f"(lo), "f"(hi)); return r;
}
__device__ __forceinline__ void fma2(ull& a, ull x, ull y) {
    asm("fma.rn.f32x2 %0, %1, %2, %0;" : "+l"(a) : "l"(x), "l"(y));
}
__device__ __forceinline__ ull add2(ull x, ull y) {
    ull r; asm("add.rn.f32x2 %0, %1, %2;" : "=l"(r) : "l"(x), "l"(y)); return r;
}
__device__ __forceinline__ void unpk(ull v, float& lo, float& hi) {
    asm("mov.b64 {%0, %1}, %2;" : "=f"(lo), "=f"(hi) : "l"(v));
}

// 128-thr blocks, 4 warps, four sequences per block (2 pairs).
// warp 2p = forward halves (t=0..511), warp 2p+1 = backward halves
// (t=1023..512) of seqs {2p,2p+1}. Emission pipeline: per chain TWO 8-row
// register buffers, refilled in one 8-LDG burst at block end (consumed two
// blocks later) -- eliminates per-step scoreboard drains on recent LDGs.
__global__ __launch_bounds__(128) void crf_k(
    const float* __restrict__ em, const int* __restrict__ tags,
    const int* __restrict__ mask,
    const float* __restrict__ startv, const float* __restrict__ endv,
    const float* __restrict__ transv,
    float* __restrict__ out)
{
    __shared__ ulonglong2 abuf[4][2][2][8];  // [warp][chain][parity][32 floats]
    __shared__ float s_af[2][2][32];
    __shared__ float s_lZ[2][2], s_sc[2][2];
    __shared__ int   s_cn[2][2];
    __shared__ double s_s[2], s_c[2];
    __shared__ double r_s[4], r_c[4];
    __shared__ int s_last;

    int tid = threadIdx.x;
    int lane = tid & 31;
    int w = tid >> 5;
    int pair = w >> 1;
    int isB = w & 1;
    int s0 = blockIdx.x * 4 + pair * 2;
    bool act = lane < T_N;
    int j = act ? lane : (T_N - 1);

    ull eM[12];
    {
        float c[24];
        #pragma unroll
        for (int s = 0; s < 24; s++) {
            if (s < T_N && act)
                c[s] = __expf(isB ? __ldg(transv + lane * T_N + s)
                                  : __ldg(transv + s * T_N + lane));
            else c[s] = 0.f;
        }
        #pragma unroll
        for (int m = 0; m < 12; m++) eM[m] = pk2(c[2*m], c[2*m+1]);
    }

    const float* pe0 = em + (size_t)s0 * (L_N * T_N);
    const float* pe1 = pe0 + (size_t)(L_N * T_N);
    const int* tg0 = tags + (size_t)s0 * L_N;
    const int* tg1 = tg0 + L_N;
    const int* mk0 = mask + (size_t)s0 * L_N;
    const int* mk1 = mk0 + L_N;

    // ===== bulk numerator: fwd sums t=1..511 (+t0), bwd t=512..1023 =====
    float num[2]; int cnum[2];
    #pragma unroll
    for (int q = 0; q < 2; q++) {
        const int* tgq = q ? tg1 : tg0;
        const int* mkq = q ? mk1 : mk0;
        const float* peq = q ? pe1 : pe0;
        float acc = 0.f; int c = 0;
        int base = isB ? 512 : 1;
        #pragma unroll 1
        for (int k = 0; k < 16; k++) {
            int t = base + k * 32 + lane;
            if (isB || t <= 511) {
                int ct = __ldg(tgq + t);
                int pt = __ldg(tgq + t - 1);
                int m  = __ldg(mkq + t);
                float ev = __ldg(peq + t * T_N + ct);
                float tv = __ldg(transv + pt * T_N + ct);
                acc += m ? (ev + tv) : 0.f;
                c += m;
            }
        }
        #pragma unroll
        for (int off = 16; off > 0; off >>= 1) {
            acc += __shfl_xor_sync(FULLM, acc, off);
            c   += __shfl_xor_sync(FULLM, c, off);
        }
        if (!isB) {
            int t0t = __ldg(tgq);
            acc += __ldg(startv + t0t) + __ldg(peq + t0t);
            c += __ldg(mkq) ? 1 : 0;
        }
        num[q] = acc; cnum[q] = c;
    }

    ulonglong2 (*bf0)[8] = abuf[w][0];
    ulonglong2 (*bf1)[8] = abuf[w][1];
    float lZ0 = 0.f, lZ1 = 0.f, inv0 = 1.f, lg0 = 0.f, inv1 = 1.f, lg1 = 0.f;
    float nv0, nv1;
    float X0[8], X1[8], Y0[8], Y1[8];

#define MATVEC(RA, RB, NX0, NX1, PREP) { \
    ulonglong2 qa0=(RA)[0],qa1=(RA)[1],qa2=(RA)[2],qa3=(RA)[3],qa4=(RA)[4],qa5=(RA)[5]; \
    ulonglong2 qb0=(RB)[0],qb1=(RB)[1],qb2=(RB)[2],qb3=(RB)[3],qb4=(RB)[4],qb5=(RB)[5]; \
    if (PREP) { float z,zz; unpk(qa0.x,z,zz); inv0=__fdividef(1.f,z); lg0=__logf(z); \
                unpk(qb0.x,z,zz); inv1=__fdividef(1.f,z); lg1=__logf(z); } \
    ull a0=0ull,a1=0ull,a2=0ull,b0=0ull,b1=0ull,b2=0ull; \
    fma2(a0,qa0.x,eM[0]);  fma2(b0,qb0.x,eM[0]); \
    fma2(a1,qa0.y,eM[1]);  fma2(b1,qb0.y,eM[1]); \
    fma2(a2,qa1.x,eM[2]);  fma2(b2,qb1.x,eM[2]); \
    fma2(a0,qa1.y,eM[3]);  fma2(b0,qb1.y,eM[3]); \
    fma2(a1,qa2.x,eM[4]);  fma2(b1,qb2.x,eM[4]); \
    fma2(a2,qa2.y,eM[5]);  fma2(b2,qb2.y,eM[5]); \
    fma2(a0,qa3.x,eM[6]);  fma2(b0,qb3.x,eM[6]); \
    fma2(a1,qa3.y,eM[7]);  fma2(b1,qb3.y,eM[7]); \
    fma2(a2,qa4.x,eM[8]);  fma2(b2,qb4.x,eM[8]); \
    fma2(a0,qa4.y,eM[9]);  fma2(b0,qb4.y,eM[9]); \
    fma2(a1,qa5.x,eM[10]); fma2(b1,qb5.x,eM[10]); \
    fma2(a2,qa5.y,eM[11]); fma2(b2,qb5.y,eM[11]); \
    ull atA=add2(add2(a0,a1),a2), atB=add2(add2(b0,b1),b2); \
    float lo,hi; unpk(atA,lo,hi); NX0=lo+hi; unpk(atB,lo,hi); NX1=lo+hi; }

#define FSTEP(E0,E1,IDX,M0,M1,DO_RN,PREP_RN) { \
    float p0=__expf((E0)[IDX]), p1=__expf((E1)[IDX]); \
    float d0,d1; MATVEC(bf0[((IDX)+1)&1], bf1[((IDX)+1)&1], d0, d1, PREP_RN); \
    float nx0=d0*p0, nx1=d1*p1; \
    nv0=(M0)?nx0:nv0; nv1=(M1)?nx1:nv1; \
    if (DO_RN){ nv0*=inv0; lZ0+=lg0; nv1*=inv1; lZ1+=lg1; } \
    ((float*)bf0[(IDX)&1])[lane]=nv0; ((float*)bf1[(IDX)&1])[lane]=nv1; \
    __syncwarp(); }

#define BSTEP(E0,E1,S,M0,M1,DO_RN,PREP_RN,LAST) { \
    float d0,d1; MATVEC(bf0[(S)&1], bf1[(S)&1], d0, d1, PREP_RN); \
    nv0=(M0)?d0:nv0; nv1=(M1)?d1:nv1; \
    if (DO_RN){ nv0*=inv0; lZ0+=lg0; nv1*=inv1; lZ1+=lg1; } \
    if (!(LAST)) { \
        float y0=__expf((E0)[((S)+7)&7])*nv0, y1=__expf((E1)[((S)+7)&7])*nv1; \
        ((float*)bf0[((S)+1)&1])[lane]=y0; ((float*)bf1[((S)+1)&1])[lane]=y1; } \
    __syncwarp(); }

    if (!isB) {
        // ============ FORWARD: t = 0..511 ============
        nv0 = act ? __expf(__ldg(startv + j) + __ldg(pe0 + j)) : 0.f;
        nv1 = act ? __expf(__ldg(startv + j) + __ldg(pe1 + j)) : 0.f;
        ((float*)bf0[0])[lane] = nv0;
        ((float*)bf1[0])[lane] = nv1;
        #pragma unroll
        for (int r = 1; r <= 8; r++) { X0[r&7]=__ldg(pe0+r*T_N+j); X1[r&7]=__ldg(pe1+r*T_N+j); }
        #pragma unroll
        for (int r = 9; r <= 16; r++) { Y0[r&7]=__ldg(pe0+r*T_N+j); Y1[r&7]=__ldg(pe1+r*T_N+j); }
        __syncwarp();

        int4 g0a=__ldg((const int4*)mk0), g1a=__ldg((const int4*)(mk0+4)), g2a=__ldg((const int4*)(mk0+8));
        int4 g0b=__ldg((const int4*)mk1), g1b=__ldg((const int4*)(mk1+4)), g2b=__ldg((const int4*)(mk1+8));

        // prologue t=1..8 (consume X)
        FSTEP(X0,X1,1,g0a.y,g0b.y,false,false)
        FSTEP(X0,X1,2,g0a.z,g0b.z,false,false)
        FSTEP(X0,X1,3,g0a.w,g0b.w,false,true)
        FSTEP(X0,X1,4,g1a.x,g1b.x,true,false)
        FSTEP(X0,X1,5,g1a.y,g1b.y,false,false)
        FSTEP(X0,X1,6,g1a.z,g1b.z,false,false)
        FSTEP(X0,X1,7,g1a.w,g1b.w,false,true)
        FSTEP(X0,X1,0,g2a.x,g2b.x,true,false)
        #pragma unroll
        for (int rr = 0; rr < 8; rr++) {
            X0[(1+rr)&7]=__ldg(pe0+(17+rr)*T_N+j);
            X1[(1+rr)&7]=__ldg(pe1+(17+rr)*T_N+j);
        }
        g0a = g2a; g0b = g2b;

        const float* r0 = pe0 + 9*T_N;
        const float* r1 = pe1 + 9*T_N;
        const int* ma = mk0 + 8;
        const int* mb = mk1 + 8;

#define FBLOCK(E0,E1) { \
        int4 h1a=__ldg((const int4*)(ma+4)), h2a=__ldg((const int4*)(ma+8)); \
        int4 h1b=__ldg((const int4*)(mb+4)), h2b=__ldg((const int4*)(mb+8)); \
        FSTEP(E0,E1,1,g0a.y,g0b.y,false,false) \
        FSTEP(E0,E1,2,g0a.z,g0b.z,false,false) \
        FSTEP(E0,E1,3,g0a.w,g0b.w,false,true) \
        FSTEP(E0,E1,4,h1a.x,h1b.x,true,false) \
        FSTEP(E0,E1,5,h1a.y,h1b.y,false,false) \
        FSTEP(E0,E1,6,h1a.z,h1b.z,false,false) \
        FSTEP(E0,E1,7,h1a.w,h1b.w,false,true) \
        FSTEP(E0,E1,0,h2a.x,h2b.x,true,false) \
        _Pragma("unroll") \
        for (int rr = 0; rr < 8; rr++) { \
            E0[(1+rr)&7]=__ldg(r0+(16+rr)*T_N+j); \
            E1[(1+rr)&7]=__ldg(r1+(16+rr)*T_N+j); \
        } \
        g0a=h2a; g0b=h2b; r0+=8*T_N; r1+=8*T_N; ma+=8; mb+=8; }

        #pragma unroll 1
        for (int sb = 0; sb < 31; sb++) {   // t = 9..504
            FBLOCK(Y0,Y1)
            FBLOCK(X0,X1)
        }
        {   // tail t=505..511 (consume Y)
            int4 h1a=__ldg((const int4*)(ma+4));
            int4 h1b=__ldg((const int4*)(mb+4));
            FSTEP(Y0,Y1,1,g0a.y,g0b.y,false,false)
            FSTEP(Y0,Y1,2,g0a.z,g0b.z,false,false)
            FSTEP(Y0,Y1,3,g0a.w,g0b.w,false,true)
            FSTEP(Y0,Y1,4,h1a.x,h1b.x,true,false)
            FSTEP(Y0,Y1,5,h1a.y,h1b.y,false,false)
            FSTEP(Y0,Y1,6,h1a.z,h1b.z,false,false)
            FSTEP(Y0,Y1,7,h1a.w,h1b.w,false,false)
        }

        s_af[pair][0][lane] = nv0;
        s_af[pair][1][lane] = nv1;
        if (lane == 0) {
            s_lZ[pair][0] = lZ0; s_lZ[pair][1] = lZ1;
            s_sc[pair][0] = num[0]; s_sc[pair][1] = num[1];
            s_cn[pair][0] = cnum[0]; s_cn[pair][1] = cnum[1];
        }
    } else {
        // ============ BACKWARD: t = 1023..512 ============
        nv0 = act ? __expf(__ldg(endv + j)) : 0.f;
        nv1 = nv0;
        ((float*)bf0[1])[lane] = __expf(__ldg(pe0 + (size_t)1023*T_N + j)) * nv0;
        ((float*)bf1[1])[lane] = __expf(__ldg(pe1 + (size_t)1023*T_N + j)) * nv1;
        #pragma unroll
        for (int r = 1015; r <= 1022; r++) { X0[r&7]=__ldg(pe0+(size_t)r*T_N+j); X1[r&7]=__ldg(pe1+(size_t)r*T_N+j); }
        #pragma unroll
        for (int r = 1007; r <= 1014; r++) { Y0[r&7]=__ldg(pe0+(size_t)r*T_N+j); Y1[r&7]=__ldg(pe1+(size_t)r*T_N+j); }
        __syncwarp();

        const float* r0 = pe0 + 1016*T_N;
        const float* r1 = pe1 + 1016*T_N;
        const int* ma = mk0 + 1016;
        const int* mb = mk1 + 1016;

#define BBLOCK(E0,E1,LASTF) { \
        int4 q0a=__ldg((const int4*)ma), q1a=__ldg((const int4*)(ma+4)); \
        int4 q0b=__ldg((const int4*)mb), q1b=__ldg((const int4*)(mb+4)); \
        BSTEP(E0,E1,7,q1a.w,q1b.w,false,true,false) \
        BSTEP(E0,E1,6,q1a.z,q1b.z,false,false,false) \
        BSTEP(E0,E1,5,q1a.y,q1b.y,false,false,false) \
        BSTEP(E0,E1,4,q1a.x,q1b.x,true,false,false) \
        BSTEP(E0,E1,3,q0a.w,q0b.w,false,true,false) \
        BSTEP(E0,E1,2,q0a.z,q0b.z,false,false,false) \
        BSTEP(E0,E1,1,q0a.y,q0b.y,false,false,false) \
        BSTEP(E0,E1,0,q0a.x,q0b.x,true,false,LASTF) \
        _Pragma("unroll") \
        for (int rr = 0; rr < 8; rr++) { \
            E0[(7+rr)&7]=__ldg(r0-17*T_N+rr*T_N+j); \
            E1[(7+rr)&7]=__ldg(r1-17*T_N+rr*T_N+j); \
        } \
        r0-=8*T_N; r1-=8*T_N; ma-=8; mb-=8; }

        #pragma unroll 1
        for (int sb = 0; sb < 32; sb++) {   // t = 1023..512
            bool lastsb = (sb == 31);
            BBLOCK(X0,X1,false)
            BBLOCK(Y0,Y1,lastsb)
        }
    }

    __syncthreads();

    if (isB) {
        float v0 = s_af[pair][0][lane] * nv0;
        float v1 = s_af[pair][1][lane] * nv1;
        #pragma unroll
        for (int off = 16; off > 0; off >>= 1) {
            v0 += __shfl_xor_sync(FULLM, v0, off);
            v1 += __shfl_xor_sync(FULLM, v1, off);
        }
        float den0 = s_lZ[pair][0] + lZ0 + __logf(v0);
        float den1 = s_lZ[pair][1] + lZ1 + __logf(v1);
        int cT0 = s_cn[pair][0] + cnum[0];
        int cT1 = s_cn[pair][1] + cnum[1];
        float sc0 = s_sc[pair][0] + num[0];
        float sc1 = s_sc[pair][1] + num[1];
        int li0 = cT0 > 0 ? cT0 - 1 : 0;
        int li1 = cT1 > 0 ? cT1 - 1 : 0;
        sc0 += __ldg(endv + __ldg(tg0 + li0));
        sc1 += __ldg(endv + __ldg(tg1 + li1));
        if (lane == 0) {
            s_s[pair] = (double)(sc0 - den0) + (double)(sc1 - den1);
            s_c[pair] = (double)(cT0 + cT1);
        }
    }
    __syncthreads();

    if (tid == 0) {
        g_ps[blockIdx.x] = s_s[0] + s_s[1];
        g_pc[blockIdx.x] = s_c[0] + s_c[1];
        __threadfence();
        unsigned d = atomicAdd(&g_ctr, 1u);
        s_last = (d == gridDim.x - 1) ? 1 : 0;
    }
    __syncthreads();

    if (s_last) {
        double ls = g_ps[tid] + g_ps[tid + 128];
        double lc = g_pc[tid] + g_pc[tid + 128];
        #pragma unroll
        for (int off = 16; off > 0; off >>= 1) {
            ls += __shfl_xor_sync(FULLM, ls, off);
            lc += __shfl_xor_sync(FULLM, lc, off);
        }
        if (lane == 0) { r_s[w] = ls; r_c[w] = lc; }
        __syncthreads();
        if (tid == 0) {
            double S = r_s[0] + r_s[1] + r_s[2] + r_s[3];
            double C = r_c[0] + r_c[1] + r_c[2] + r_c[3];
            out[0] = (float)(S / C);
            atomicExch(&g_ctr, 0u);
        }
    }
}

extern "C" void kernel_launch(void* const* d_in, const int* in_sizes, int n_in,
                              void* d_out, int out_size) {
    const float* em     = (const float*)d_in[0];
    const int* tags     = (const int*)d_in[1];
    const int* mask     = (const int*)d_in[2];
    const float* startv = (const float*)d_in[3];
    const float* endv   = (const float*)d_in[4];
    const float* trans  = (const float*)d_in[5];

    crf_k<<<B_N / 4, 128>>>(em, tags, mask, startv, endv, trans, (float*)d_out);
}

// round 16
// speedup vs baseline: 4.8620x; 1.1066x over previous
#include <cuda_runtime.h>

#define FULLM 0xffffffffu
#define B_N 1024
#define L_N 1024
#define T_N 21

typedef unsigned long long ull;

__device__ double g_ps[512];
__device__ double g_pc[512];
__device__ unsigned int g_ctr;   // static zero-init; self-resetting

__device__ __forceinline__ ull pk2(float lo, float hi) {
    ull r; asm("mov.b64 %0, {%1, %2};" : "=l"(r) : "f"(lo), "f"(hi)); return r;
}
__device__ __forceinline__ void fma2(ull& a, ull x, ull y) {
    asm("fma.rn.f32x2 %0, %1, %2, %0;" : "+l"(a) : "l"(x), "l"(y));
}
__device__ __forceinline__ ull add2(ull x, ull y) {
    ull r; asm("add.rn.f32x2 %0, %1, %2;" : "=l"(r) : "l"(x), "l"(y)); return r;
}
__device__ __forceinline__ void unpk(ull v, float& lo, float& hi) {
    asm("mov.b64 {%0, %1}, %2;" : "=f"(lo), "=f"(hi) : "l"(v));
}

// 128-thr blocks, 4 warps, TWO sequences per block, ONE chain per warp:
// warp 2p = forward half (t=0..511), warp 2p+1 = backward half (t=1023..512)
// of sequence p. 2048 warps total -> 3.46 warps/SMSP (vs 1.73 with 2
// chains/warp): issue supply covers the STS->sync->LDS round-trip latency.
// Emission pipeline: TWO 8-row register buffers per warp, refilled in one
// 8-LDG burst per 8-step block, consumed two blocks later.
__global__ __launch_bounds__(128) void crf_k(
    const float* __restrict__ em, const int* __restrict__ tags,
    const int* __restrict__ mask,
    const float* __restrict__ startv, const float* __restrict__ endv,
    const float* __restrict__ transv,
    float* __restrict__ out)
{
    __shared__ ulonglong2 abuf[4][2][8];  // [warp][parity][32 floats]
    __shared__ float s_af[2][32];
    __shared__ float s_lZ[2], s_sc[2];
    __shared__ int   s_cn[2];
    __shared__ double s_s[2], s_c[2];
    __shared__ double r_s[4], r_c[4];
    __shared__ int s_last;

    int tid = threadIdx.x;
    int lane = tid & 31;
    int w = tid >> 5;
    int pair = w >> 1;
    int isB = w & 1;
    int seq = blockIdx.x * 2 + pair;
    bool act = lane < T_N;
    int j = act ? lane : (T_N - 1);

    // fwd warps: column 'lane' of E=exp(trans); bwd warps: row 'lane'.
    ull eM[12];
    {
        float c[24];
        #pragma unroll
        for (int s = 0; s < 24; s++) {
            if (s < T_N && act)
                c[s] = __expf(isB ? __ldg(transv + lane * T_N + s)
                                  : __ldg(transv + s * T_N + lane));
            else c[s] = 0.f;
        }
        #pragma unroll
        for (int m = 0; m < 12; m++) eM[m] = pk2(c[2*m], c[2*m+1]);
    }

    const float* pe = em + (size_t)seq * (L_N * T_N);
    const int* tg = tags + (size_t)seq * L_N;
    const int* mk = mask + (size_t)seq * L_N;

    // ===== bulk numerator: fwd sums t=1..511 (+t0), bwd t=512..1023 =====
    float num; int cnum;
    {
        float acc = 0.f; int c = 0;
        int base = isB ? 512 : 1;
        #pragma unroll 1
        for (int k = 0; k < 16; k++) {
            int t = base + k * 32 + lane;
            if (isB || t <= 511) {
                int ct = __ldg(tg + t);
                int pt = __ldg(tg + t - 1);
                int m  = __ldg(mk + t);
                float ev = __ldg(pe + t * T_N + ct);
                float tv = __ldg(transv + pt * T_N + ct);
                acc += m ? (ev + tv) : 0.f;
                c += m;
            }
        }
        #pragma unroll
        for (int off = 16; off > 0; off >>= 1) {
            acc += __shfl_xor_sync(FULLM, acc, off);
            c   += __shfl_xor_sync(FULLM, c, off);
        }
        if (!isB) {
            int t0t = __ldg(tg);
            acc += __ldg(startv + t0t) + __ldg(pe + t0t);
            c += __ldg(mk) ? 1 : 0;
        }
        num = acc; cnum = c;
    }

    ulonglong2 (*bf)[8] = abuf[w];
    float lZ = 0.f, inv = 1.f, lg = 0.f;
    float nv;
    float X[8], Y[8];

#define MATVEC(RA, NX, PREP) { \
    ulonglong2 q0=(RA)[0],q1=(RA)[1],q2=(RA)[2],q3=(RA)[3],q4=(RA)[4],q5=(RA)[5]; \
    if (PREP) { float z,zz; unpk(q0.x,z,zz); inv=__fdividef(1.f,z); lg=__logf(z); } \
    ull a0=0ull,a1=0ull,a2=0ull; \
    fma2(a0,q0.x,eM[0]);  fma2(a1,q0.y,eM[1]);  fma2(a2,q1.x,eM[2]); \
    fma2(a0,q1.y,eM[3]);  fma2(a1,q2.x,eM[4]);  fma2(a2,q2.y,eM[5]); \
    fma2(a0,q3.x,eM[6]);  fma2(a1,q3.y,eM[7]);  fma2(a2,q4.x,eM[8]); \
    fma2(a0,q4.y,eM[9]);  fma2(a1,q5.x,eM[10]); fma2(a2,q5.y,eM[11]); \
    ull at=add2(add2(a0,a1),a2); \
    float lo,hi; unpk(at,lo,hi); NX=lo+hi; }

#define FSTEP(E,IDX,M,DO_RN,PREP_RN) { \
    float p=__expf((E)[IDX]); \
    float d; MATVEC(bf[((IDX)+1)&1], d, PREP_RN); \
    float nx=d*p; \
    nv=(M)?nx:nv; \
    if (DO_RN){ nv*=inv; lZ+=lg; } \
    ((float*)bf[(IDX)&1])[lane]=nv; \
    __syncwarp(); }

#define BSTEP(E,S,M,DO_RN,PREP_RN,LAST) { \
    float d; MATVEC(bf[(S)&1], d, PREP_RN); \
    nv=(M)?d:nv; \
    if (DO_RN){ nv*=inv; lZ+=lg; } \
    if (!(LAST)) { \
        float y=__expf((E)[((S)+7)&7])*nv; \
        ((float*)bf[((S)+1)&1])[lane]=y; } \
    __syncwarp(); }

    if (!isB) {
        // ============ FORWARD: t = 0..511 ============
        nv = act ? __expf(__ldg(startv + j) + __ldg(pe + j)) : 0.f;
        ((float*)bf[0])[lane] = nv;
        #pragma unroll
        for (int r = 1; r <= 8; r++) X[r&7] = __ldg(pe + r*T_N + j);
        #pragma unroll
        for (int r = 9; r <= 16; r++) Y[r&7] = __ldg(pe + r*T_N + j);
        __syncwarp();

        int4 g0 = __ldg((const int4*)mk), g1 = __ldg((const int4*)(mk+4)), g2 = __ldg((const int4*)(mk+8));

        // prologue t=1..8 (consume X)
        FSTEP(X,1,g0.y,false,false)
        FSTEP(X,2,g0.z,false,false)
        FSTEP(X,3,g0.w,false,true)
        FSTEP(X,4,g1.x,true,false)
        FSTEP(X,5,g1.y,false,false)
        FSTEP(X,6,g1.z,false,false)
        FSTEP(X,7,g1.w,false,true)
        FSTEP(X,0,g2.x,true,false)
        #pragma unroll
        for (int rr = 0; rr < 8; rr++) X[(1+rr)&7] = __ldg(pe + (17+rr)*T_N + j);
        g0 = g2;

        const float* r0 = pe + 9*T_N;
        const int* ma = mk + 8;

#define FBLOCK(E) { \
        int4 h1=__ldg((const int4*)(ma+4)), h2=__ldg((const int4*)(ma+8)); \
        FSTEP(E,1,g0.y,false,false) \
        FSTEP(E,2,g0.z,false,false) \
        FSTEP(E,3,g0.w,false,true) \
        FSTEP(E,4,h1.x,true,false) \
        FSTEP(E,5,h1.y,false,false) \
        FSTEP(E,6,h1.z,false,false) \
        FSTEP(E,7,h1.w,false,true) \
        FSTEP(E,0,h2.x,true,false) \
        _Pragma("unroll") \
        for (int rr = 0; rr < 8; rr++) E[(1+rr)&7] = __ldg(r0 + (16+rr)*T_N + j); \
        g0=h2; r0+=8*T_N; ma+=8; }

        #pragma unroll 1
        for (int sb = 0; sb < 31; sb++) {   // t = 9..504
            FBLOCK(Y)
            FBLOCK(X)
        }
        {   // tail t=505..511 (consume Y)
            int4 h1 = __ldg((const int4*)(ma+4));
            FSTEP(Y,1,g0.y,false,false)
            FSTEP(Y,2,g0.z,false,false)
            FSTEP(Y,3,g0.w,false,true)
            FSTEP(Y,4,h1.x,true,false)
            FSTEP(Y,5,h1.y,false,false)
            FSTEP(Y,6,h1.z,false,false)
            FSTEP(Y,7,h1.w,false,false)
        }

        s_af[pair][lane] = nv;
        if (lane == 0) { s_lZ[pair] = lZ; s_sc[pair] = num; s_cn[pair] = cnum; }
    } else {
        // ============ BACKWARD: t = 1023..512 ============
        nv = act ? __expf(__ldg(endv + j)) : 0.f;
        ((float*)bf[1])[lane] = __expf(__ldg(pe + (size_t)1023*T_N + j)) * nv;
        #pragma unroll
        for (int r = 1015; r <= 1022; r++) X[r&7] = __ldg(pe + (size_t)r*T_N + j);
        #pragma unroll
        for (int r = 1007; r <= 1014; r++) Y[r&7] = __ldg(pe + (size_t)r*T_N + j);
        __syncwarp();

        const float* r0 = pe + 1016*T_N;
        const int* ma = mk + 1016;

#define BBLOCK(E,LASTF) { \
        int4 q0m=__ldg((const int4*)ma), q1m=__ldg((const int4*)(ma+4)); \
        BSTEP(E,7,q1m.w,false,true,false) \
        BSTEP(E,6,q1m.z,false,false,false) \
        BSTEP(E,5,q1m.y,false,false,false) \
        BSTEP(E,4,q1m.x,true,false,false) \
        BSTEP(E,3,q0m.w,false,true,false) \
        BSTEP(E,2,q0m.z,false,false,false) \
        BSTEP(E,1,q0m.y,false,false,false) \
        BSTEP(E,0,q0m.x,true,false,LASTF) \
        _Pragma("unroll") \
        for (int rr = 0; rr < 8; rr++) E[(7+rr)&7] = __ldg(r0 - 17*T_N + rr*T_N + j); \
        r0-=8*T_N; ma-=8; }

        #pragma unroll 1
        for (int sb = 0; sb < 32; sb++) {   // t = 1023..512
            bool lastsb = (sb == 31);
            BBLOCK(X,false)
            BBLOCK(Y,lastsb)
        }
    }

    __syncthreads();

    if (isB) {
        // combine: Z = alpha_511 . beta_511
        float v = s_af[pair][lane] * nv;
        #pragma unroll
        for (int off = 16; off > 0; off >>= 1) v += __shfl_xor_sync(FULLM, v, off);
        float den = s_lZ[pair] + lZ + __logf(v);
        int cT = s_cn[pair] + cnum;
        float sc = s_sc[pair] + num;
        int li = cT > 0 ? cT - 1 : 0;
        sc += __ldg(endv + __ldg(tg + li));
        if (lane == 0) { s_s[pair] = (double)(sc - den); s_c[pair] = (double)cT; }
    }
    __syncthreads();

    if (tid == 0) {
        g_ps[blockIdx.x] = s_s[0] + s_s[1];
        g_pc[blockIdx.x] = s_c[0] + s_c[1];
        __threadfence();
        unsigned d = atomicAdd(&g_ctr, 1u);
        s_last = (d == gridDim.x - 1) ? 1 : 0;
    }
    __syncthreads();

    if (s_last) {
        double ls = g_ps[tid] + g_ps[tid + 128] + g_ps[tid + 256] + g_ps[tid + 384];
        double lc = g_pc[tid] + g_pc[tid + 128] + g_pc[tid + 256] + g_pc[tid + 384];
        #pragma unroll
        for (int off = 16; off > 0; off >>= 1) {
            ls += __shfl_xor_sync(FULLM, ls, off);
            lc += __shfl_xor_sync(FULLM, lc, off);
        }
        if (lane == 0) { r_s[w] = ls; r_c[w] = lc; }
        __syncthreads();
        if (tid == 0) {
            double S = r_s[0] + r_s[1] + r_s[2] + r_s[3];
            double C = r_c[0] + r_c[1] + r_c[2] + r_c[3];
            out[0] = (float)(S / C);
            atomicExch(&g_ctr, 0u);   // self-reset for next graph replay
        }
    }
}

extern "C" void kernel_launch(void* const* d_in, const int* in_sizes, int n_in,
                              void* d_out, int out_size) {
    const float* em     = (const float*)d_in[0];
    const int* tags     = (const int*)d_in[1];
    const int* mask     = (const int*)d_in[2];
    const float* startv = (const float*)d_in[3];
    const float* endv   = (const float*)d_in[4];
    const float* trans  = (const float*)d_in[5];

    crf_k<<<B_N / 2, 128>>>(em, tags, mask, startv, endv, trans, (float*)d_out);
}

// round 17
// speedup vs baseline: 5.3751x; 1.1055x over previous
#include <cuda_runtime.h>
#include <cuda_bf16.h>

#define FULLM 0xffffffffu
#define B_N 1024
#define L_N 1024
#define T_N 21

__device__ double g_ps[512];
__device__ double g_pc[512];
__device__ unsigned int g_ctr;   // static zero-init; self-resetting

__device__ __forceinline__ __nv_bfloat162 B2(unsigned int x) {
    __nv_bfloat162 r;
    *reinterpret_cast<unsigned int*>(&r) = x;
    return r;
}

// 128-thr blocks, 4 warps, TWO sequences per block, ONE chain per warp:
// warp 2p = forward half (t=0..511), warp 2p+1 = backward half (t=1023..512).
// Alpha broadcast in BF16 (48B/row instead of 96B): halves the smem-crossbar
// return bandwidth, which R16 profiling showed to be the binding resource
// (~330-380 cyc/SM-step). Matvec = 12 HFMA2.BF16 with pre-packed bf16x2 E.
// All bookkeeping (carry, renorm, logZ, score) stays fp32.
__global__ __launch_bounds__(128) void crf_k(
    const float* __restrict__ em, const int* __restrict__ tags,
    const int* __restrict__ mask,
    const float* __restrict__ startv, const float* __restrict__ endv,
    const float* __restrict__ transv,
    float* __restrict__ out)
{
    __shared__ uint4 abuf[4][2][3];   // [warp][parity][24 bf16 = 48B]
    __shared__ float s_af[2][32];
    __shared__ float s_lZ[2], s_sc[2];
    __shared__ int   s_cn[2];
    __shared__ double s_s[2], s_c[2];
    __shared__ double r_s[4], r_c[4];
    __shared__ int s_last;

    int tid = threadIdx.x;
    int lane = tid & 31;
    int w = tid >> 5;
    int pair = w >> 1;
    int isB = w & 1;
    int seq = blockIdx.x * 2 + pair;
    bool act = lane < T_N;
    int j = act ? lane : (T_N - 1);

    // fwd warps: column 'lane' of E=exp(trans); bwd warps: row 'lane'.
    // Packed as bf16x2 over consecutive i (rows 21..23 zero).
    __nv_bfloat162 eM[12];
    {
        float c[24];
        #pragma unroll
        for (int s = 0; s < 24; s++) {
            if (s < T_N && act)
                c[s] = __expf(isB ? __ldg(transv + lane * T_N + s)
                                  : __ldg(transv + s * T_N + lane));
            else c[s] = 0.f;
        }
        #pragma unroll
        for (int m = 0; m < 12; m++) eM[m] = __floats2bfloat162_rn(c[2*m], c[2*m+1]);
    }

    const float* pe = em + (size_t)seq * (L_N * T_N);
    const int* tg = tags + (size_t)seq * L_N;
    const int* mk = mask + (size_t)seq * L_N;

    // ===== bulk numerator: fwd sums t=1..511 (+t0), bwd t=512..1023 =====
    float num; int cnum;
    {
        float acc = 0.f; int c = 0;
        int base = isB ? 512 : 1;
        #pragma unroll 1
        for (int k = 0; k < 16; k++) {
            int t = base + k * 32 + lane;
            if (isB || t <= 511) {
                int ct = __ldg(tg + t);
                int pt = __ldg(tg + t - 1);
                int m  = __ldg(mk + t);
                float ev = __ldg(pe + t * T_N + ct);
                float tv = __ldg(transv + pt * T_N + ct);
                acc += m ? (ev + tv) : 0.f;
                c += m;
            }
        }
        #pragma unroll
        for (int off = 16; off > 0; off >>= 1) {
            acc += __shfl_xor_sync(FULLM, acc, off);
            c   += __shfl_xor_sync(FULLM, c, off);
        }
        if (!isB) {
            int t0t = __ldg(tg);
            acc += __ldg(startv + t0t) + __ldg(pe + t0t);
            c += __ldg(mk) ? 1 : 0;
        }
        num = acc; cnum = c;
    }

    uint4 (*bfu)[3] = abuf[w];
    __nv_bfloat16* bp0 = (__nv_bfloat16*)abuf[w][0];
    __nv_bfloat16* bp1 = (__nv_bfloat16*)abuf[w][1];

    // zero the pad entries (21..23) of both parities, written once
    if (lane >= T_N && lane < 24) {
        bp0[lane] = __float2bfloat16_rn(0.f);
        bp1[lane] = __float2bfloat16_rn(0.f);
    }

    float lZ = 0.f, inv = 1.f, lg = 0.f;
    float nv;
    float X[8], Y[8];

#define MATVEC(RA, NX, PREP) { \
    uint4 u0=(RA)[0], u1=(RA)[1], u2=(RA)[2]; \
    if (PREP) { float z=__uint_as_float(u0.x<<16); inv=__fdividef(1.f,z); lg=__logf(z); } \
    __nv_bfloat162 A0=__floats2bfloat162_rn(0.f,0.f), A1=A0, A2=A0; \
    A0=__hfma2(B2(u0.x),eM[0],A0); A1=__hfma2(B2(u0.y),eM[1],A1); A2=__hfma2(B2(u0.z),eM[2],A2); \
    A0=__hfma2(B2(u0.w),eM[3],A0); A1=__hfma2(B2(u1.x),eM[4],A1); A2=__hfma2(B2(u1.y),eM[5],A2); \
    A0=__hfma2(B2(u1.z),eM[6],A0); A1=__hfma2(B2(u1.w),eM[7],A1); A2=__hfma2(B2(u2.x),eM[8],A2); \
    A0=__hfma2(B2(u2.y),eM[9],A0); A1=__hfma2(B2(u2.z),eM[10],A1); A2=__hfma2(B2(u2.w),eM[11],A2); \
    __nv_bfloat162 S=__hadd2(__hadd2(A0,A1),A2); \
    float2 ff=__bfloat1622float2(S); \
    NX=ff.x+ff.y; }

#define FSTEP(E,IDX,M,DO_RN,PREP_RN) { \
    float p=__expf((E)[IDX]); \
    float d; MATVEC(bfu[((IDX)+1)&1], d, PREP_RN); \
    float nx=d*p; \
    nv=(M)?nx:nv; \
    if (DO_RN){ nv*=inv; lZ+=lg; } \
    if (act) ((((IDX)&1)?bp1:bp0))[lane]=__float2bfloat16_rn(nv); \
    __syncwarp(); }

#define BSTEP(E,S,M,DO_RN,PREP_RN,LAST) { \
    float d; MATVEC(bfu[(S)&1], d, PREP_RN); \
    nv=(M)?d:nv; \
    if (DO_RN){ nv*=inv; lZ+=lg; } \
    if (!(LAST)) { \
        float y=__expf((E)[((S)+7)&7])*nv; \
        if (act) (((((S)+1)&1)?bp1:bp0))[lane]=__float2bfloat16_rn(y); } \
    __syncwarp(); }

    if (!isB) {
        // ============ FORWARD: t = 0..511 ============
        nv = act ? __expf(__ldg(startv + j) + __ldg(pe + j)) : 0.f;
        if (act) bp0[lane] = __float2bfloat16_rn(nv);
        #pragma unroll
        for (int r = 1; r <= 8; r++) X[r&7] = __ldg(pe + r*T_N + j);
        #pragma unroll
        for (int r = 9; r <= 16; r++) Y[r&7] = __ldg(pe + r*T_N + j);
        __syncwarp();

        int4 g0 = __ldg((const int4*)mk), g1 = __ldg((const int4*)(mk+4)), g2 = __ldg((const int4*)(mk+8));

        // prologue t=1..8 (consume X)
        FSTEP(X,1,g0.y,false,false)
        FSTEP(X,2,g0.z,false,false)
        FSTEP(X,3,g0.w,false,true)
        FSTEP(X,4,g1.x,true,false)
        FSTEP(X,5,g1.y,false,false)
        FSTEP(X,6,g1.z,false,false)
        FSTEP(X,7,g1.w,false,true)
        FSTEP(X,0,g2.x,true,false)
        #pragma unroll
        for (int rr = 0; rr < 8; rr++) X[(1+rr)&7] = __ldg(pe + (17+rr)*T_N + j);
        g0 = g2;

        const float* r0 = pe + 9*T_N;
        const int* ma = mk + 8;

#define FBLOCK(E) { \
        int4 h1=__ldg((const int4*)(ma+4)), h2=__ldg((const int4*)(ma+8)); \
        FSTEP(E,1,g0.y,false,false) \
        FSTEP(E,2,g0.z,false,false) \
        FSTEP(E,3,g0.w,false,true) \
        FSTEP(E,4,h1.x,true,false) \
        FSTEP(E,5,h1.y,false,false) \
        FSTEP(E,6,h1.z,false,false) \
        FSTEP(E,7,h1.w,false,true) \
        FSTEP(E,0,h2.x,true,false) \
        _Pragma("unroll") \
        for (int rr = 0; rr < 8; rr++) E[(1+rr)&7] = __ldg(r0 + (16+rr)*T_N + j); \
        g0=h2; r0+=8*T_N; ma+=8; }

        #pragma unroll 1
        for (int sb = 0; sb < 31; sb++) {   // t = 9..504
            FBLOCK(Y)
            FBLOCK(X)
        }
        {   // tail t=505..511 (consume Y)
            int4 h1 = __ldg((const int4*)(ma+4));
            FSTEP(Y,1,g0.y,false,false)
            FSTEP(Y,2,g0.z,false,false)
            FSTEP(Y,3,g0.w,false,true)
            FSTEP(Y,4,h1.x,true,false)
            FSTEP(Y,5,h1.y,false,false)
            FSTEP(Y,6,h1.z,false,false)
            FSTEP(Y,7,h1.w,false,false)
        }

        s_af[pair][lane] = nv;
        if (lane == 0) { s_lZ[pair] = lZ; s_sc[pair] = num; s_cn[pair] = cnum; }
    } else {
        // ============ BACKWARD: t = 1023..512 ============
        nv = act ? __expf(__ldg(endv + j)) : 0.f;
        if (act) bp1[lane] = __float2bfloat16_rn(__expf(__ldg(pe + (size_t)1023*T_N + j)) * nv);
        #pragma unroll
        for (int r = 1015; r <= 1022; r++) X[r&7] = __ldg(pe + (size_t)r*T_N + j);
        #pragma unroll
        for (int r = 1007; r <= 1014; r++) Y[r&7] = __ldg(pe + (size_t)r*T_N + j);
        __syncwarp();

        const float* r0 = pe + 1016*T_N;
        const int* ma = mk + 1016;

#define BBLOCK(E,LASTF) { \
        int4 q0m=__ldg((const int4*)ma), q1m=__ldg((const int4*)(ma+4)); \
        BSTEP(E,7,q1m.w,false,true,false) \
        BSTEP(E,6,q1m.z,false,false,false) \
        BSTEP(E,5,q1m.y,false,false,false) \
        BSTEP(E,4,q1m.x,true,false,false) \
        BSTEP(E,3,q0m.w,false,true,false) \
        BSTEP(E,2,q0m.z,false,false,false) \
        BSTEP(E,1,q0m.y,false,false,false) \
        BSTEP(E,0,q0m.x,true,false,LASTF) \
        _Pragma("unroll") \
        for (int rr = 0; rr < 8; rr++) E[(7+rr)&7] = __ldg(r0 - 17*T_N + rr*T_N + j); \
        r0-=8*T_N; ma-=8; }

        #pragma unroll 1
        for (int sb = 0; sb < 32; sb++) {   // t = 1023..512
            bool lastsb = (sb == 31);
            BBLOCK(X,false)
            BBLOCK(Y,lastsb)
        }
    }

    __syncthreads();

    if (isB) {
        // combine: Z = alpha_511 . beta_511  (fp32 junction values)
        float v = s_af[pair][lane] * nv;
        #pragma unroll
        for (int off = 16; off > 0; off >>= 1) v += __shfl_xor_sync(FULLM, v, off);
        float den = s_lZ[pair] + lZ + __logf(v);
        int cT = s_cn[pair] + cnum;
        float sc = s_sc[pair] + num;
        int li = cT > 0 ? cT - 1 : 0;
        sc += __ldg(endv + __ldg(tg + li));
        if (lane == 0) { s_s[pair] = (double)(sc - den); s_c[pair] = (double)cT; }
    }
    __syncthreads();

    if (tid == 0) {
        g_ps[blockIdx.x] = s_s[0] + s_s[1];
        g_pc[blockIdx.x] = s_c[0] + s_c[1];
        __threadfence();
        unsigned d = atomicAdd(&g_ctr, 1u);
        s_last = (d == gridDim.x - 1) ? 1 : 0;
    }
    __syncthreads();

    if (s_last) {
        double ls = g_ps[tid] + g_ps[tid + 128] + g_ps[tid + 256] + g_ps[tid + 384];
        double lc = g_pc[tid] + g_pc[tid + 128] + g_pc[tid + 256] + g_pc[tid + 384];
        #pragma unroll
        for (int off = 16; off > 0; off >>= 1) {
            ls += __shfl_xor_sync(FULLM, ls, off);
            lc += __shfl_xor_sync(FULLM, lc, off);
        }
        if (lane == 0) { r_s[w] = ls; r_c[w] = lc; }
        __syncthreads();
        if (tid == 0) {
            double S = r_s[0] + r_s[1] + r_s[2] + r_s[3];
            double C = r_c[0] + r_c[1] + r_c[2] + r_c[3];
            out[0] = (float)(S / C);
            atomicExch(&g_ctr, 0u);   // self-reset for next graph replay
        }
    }
}

extern "C" void kernel_launch(void* const* d_in, const int* in_sizes, int n_in,
                              void* d_out, int out_size) {
    const float* em     = (const float*)d_in[0];
    const int* tags     = (const int*)d_in[1];
    const int* mask     = (const int*)d_in[2];
    const float* startv = (const float*)d_in[3];
    const float* endv   = (const float*)d_in[4];
    const float* trans  = (const float*)d_in[5];

    crf_k<<<B_N / 2, 128>>>(em, tags, mask, startv, endv, trans, (float*)d_out);
}